// round 1
// baseline (speedup 1.0000x reference)
#include <cuda_runtime.h>
#include <cstdint>

// W4 group-quantized GEMM: out[M,N] = x[M,K] @ dequant(qweight)[K,N] + bias
//   qweight: int32 [K, N/8], 8 nibbles per int32 along N
//   zeros:   int32 [K/128, N], scales: fp32 [K/128, N], GROUP=128
// Round-1 baseline: SIMT fp32 GEMM with packed fma.rn.f32x2 (2 FMA/instr),
// 128x128x16 tiling, 8x8 microtile/thread, double-buffered SMEM, dequant into
// SMEM on load, per-group scale/zero cached in SMEM.

#define BM 128
#define BN 128
#define BK 16
#define PADA 4
#define PADB 4

typedef unsigned long long ull;

__device__ __forceinline__ ull pack2(float v) {
    ull r;
    asm("mov.b64 %0, {%1, %1};" : "=l"(r) : "f"(v));
    return r;
}
__device__ __forceinline__ void ffma2(ull& d, ull a, ull b) {
    asm("fma.rn.f32x2 %0, %1, %2, %0;" : "+l"(d) : "l"(a), "l"(b));
}

__launch_bounds__(256, 2)
__global__ void wq4_gemm_kernel(const float* __restrict__ x,
                                const int*   __restrict__ qw,
                                const int*   __restrict__ zeros,
                                const float* __restrict__ scales,
                                const float* __restrict__ bias,
                                float* __restrict__ out,
                                int M, int K, int N)
{
    __shared__ float As[2][BK][BM + PADA];   // As[k][m] (transposed x tile)
    __shared__ float Bs[2][BK][BN + PADB];   // dequantized weights
    __shared__ float sS[BN];                 // group scales for this n-strip
    __shared__ float zS[BN];                 // group zeros (as float)

    const int tid = threadIdx.x;
    const int bn = blockIdx.x;
    const int bm = blockIdx.y;
    const int n0 = bn * BN;
    const int m0 = bm * BM;
    const int tx = tid & 15;       // 0..15 -> n microtile
    const int ty = tid >> 4;       // 0..15 -> m microtile

    // A tile load mapping: 128 rows x 16 cols, 2 float4 per thread
    const int arow = tid >> 2;            // 0..63 (and +64)
    const int acol = (tid & 3) * 4;       // 0,4,8,12
    // B tile load mapping: 16 rows x 16 int32 per row, 1 int32 per thread
    const int krow = tid >> 4;            // 0..15
    const int kcol = tid & 15;            // 0..15
    const int nq   = N >> 3;

    const float* xA = x + (size_t)(m0 + arow) * K + acol;
    const int*   qP = qw + (size_t)krow * nq + (n0 >> 3) + kcol;

    ull acc[8][4];
#pragma unroll
    for (int i = 0; i < 8; i++)
#pragma unroll
        for (int j = 0; j < 4; j++) acc[i][j] = 0ull;

    const int ntiles = K / BK;

    // group-0 scale/zero cache
    if (tid < BN) {
        sS[tid] = scales[(size_t)n0 + tid];
        zS[tid] = (float)zeros[(size_t)n0 + tid];
    }

    // prologue: prefetch tile 0
    float4 av0 = *(const float4*)(xA);
    float4 av1 = *(const float4*)(xA + (size_t)64 * K);
    int    qv  = qP[0];
    __syncthreads();   // sS/zS visible

    // store tile 0 -> buf 0
    {
        As[0][acol + 0][arow]      = av0.x;
        As[0][acol + 1][arow]      = av0.y;
        As[0][acol + 2][arow]      = av0.z;
        As[0][acol + 3][arow]      = av0.w;
        As[0][acol + 0][arow + 64] = av1.x;
        As[0][acol + 1][arow + 64] = av1.y;
        As[0][acol + 2][arow + 64] = av1.z;
        As[0][acol + 3][arow + 64] = av1.w;
        float w[8];
#pragma unroll
        for (int j = 0; j < 8; j++) {
            int nib = (qv >> (4 * j)) & 0xF;
            w[j] = ((float)nib - zS[kcol * 8 + j]) * sS[kcol * 8 + j];
        }
        *(float4*)&Bs[0][krow][kcol * 8]     = make_float4(w[0], w[1], w[2], w[3]);
        *(float4*)&Bs[0][krow][kcol * 8 + 4] = make_float4(w[4], w[5], w[6], w[7]);
    }
    __syncthreads();

    int buf = 0;
    for (int kt = 0; kt < ntiles; kt++) {
        const int nxt = buf ^ 1;
        const bool has_next = (kt + 1) < ntiles;
        float4 nav0, nav1;
        int nqv = 0;
        if (has_next) {
            const float* xn = xA + (size_t)(kt + 1) * BK;
            nav0 = *(const float4*)(xn);
            nav1 = *(const float4*)(xn + (size_t)64 * K);
            nqv  = qP[(size_t)(kt + 1) * BK * nq];
        }

        // ---- compute on buf ----
#pragma unroll
        for (int kk = 0; kk < BK; kk++) {
            float4 a0 = *(const float4*)&As[buf][kk][ty * 8];
            float4 a1 = *(const float4*)&As[buf][kk][ty * 8 + 4];
            const ull* bp = (const ull*)&Bs[buf][kk][tx * 8];
            ull bb0 = bp[0], bb1 = bp[1], bb2 = bp[2], bb3 = bp[3];
            float av[8] = {a0.x, a0.y, a0.z, a0.w, a1.x, a1.y, a1.z, a1.w};
#pragma unroll
            for (int i = 0; i < 8; i++) {
                ull a2 = pack2(av[i]);
                ffma2(acc[i][0], a2, bb0);
                ffma2(acc[i][1], a2, bb1);
                ffma2(acc[i][2], a2, bb2);
                ffma2(acc[i][3], a2, bb3);
            }
        }

        if (has_next) {
            const int g0 = (kt * BK) >> 7;
            const int g1 = ((kt + 1) * BK) >> 7;
            if (g1 != g0) {
                // refresh group scale/zero cache; barrier before anyone uses it
                if (tid < BN) {
                    sS[tid] = scales[(size_t)g1 * N + n0 + tid];
                    zS[tid] = (float)zeros[(size_t)g1 * N + n0 + tid];
                }
                __syncthreads();
            }
            // ---- store prefetched tile -> nxt ----
            As[nxt][acol + 0][arow]      = nav0.x;
            As[nxt][acol + 1][arow]      = nav0.y;
            As[nxt][acol + 2][arow]      = nav0.z;
            As[nxt][acol + 3][arow]      = nav0.w;
            As[nxt][acol + 0][arow + 64] = nav1.x;
            As[nxt][acol + 1][arow + 64] = nav1.y;
            As[nxt][acol + 2][arow + 64] = nav1.z;
            As[nxt][acol + 3][arow + 64] = nav1.w;
            float w[8];
#pragma unroll
            for (int j = 0; j < 8; j++) {
                int nib = (nqv >> (4 * j)) & 0xF;
                w[j] = ((float)nib - zS[kcol * 8 + j]) * sS[kcol * 8 + j];
            }
            *(float4*)&Bs[nxt][krow][kcol * 8]     = make_float4(w[0], w[1], w[2], w[3]);
            *(float4*)&Bs[nxt][krow][kcol * 8 + 4] = make_float4(w[4], w[5], w[6], w[7]);
        }
        __syncthreads();
        buf = nxt;
    }

    // ---- epilogue: add bias, write out ----
    float bcol[8];
#pragma unroll
    for (int j = 0; j < 8; j++) bcol[j] = bias[n0 + tx * 8 + j];
#pragma unroll
    for (int i = 0; i < 8; i++) {
        const int row = m0 + ty * 8 + i;
        float2* orow = (float2*)(out + (size_t)row * N + n0 + tx * 8);
#pragma unroll
        for (int j = 0; j < 4; j++) {
            float lo = __uint_as_float((unsigned)(acc[i][j] & 0xffffffffu));
            float hi = __uint_as_float((unsigned)(acc[i][j] >> 32));
            orow[j] = make_float2(lo + bcol[2 * j], hi + bcol[2 * j + 1]);
        }
    }
}

extern "C" void kernel_launch(void* const* d_in, const int* in_sizes, int n_in,
                              void* d_out, int out_size)
{
    const float* x      = (const float*)d_in[0];
    const int*   qw     = (const int*)d_in[1];
    const int*   zeros  = (const int*)d_in[2];
    const float* scales = (const float*)d_in[3];
    const float* bias   = (const float*)d_in[4];
    float* out = (float*)d_out;

    const int N = in_sizes[4];                  // 11008
    const int K = (int)(((long long)in_sizes[1] * 8) / N);  // 4096
    const int M = in_sizes[0] / K;              // 4096

    dim3 grid(N / BN, M / BM);   // n fastest -> wave covers all n-strips, A reuse in L2
    wq4_gemm_kernel<<<grid, 256>>>(x, qw, zeros, scales, bias, out, M, K, N);
}

// round 3
// speedup vs baseline: 2.0263x; 2.0263x over previous
#include <cuda_runtime.h>
#include <cstdint>

// W4 group-quant GEMM via mma.sync.m16n8k8.tf32 (base sm_103 PTX; no tcgen05 —
// harness PTX target is plain sm_103, which rejects all 'a'-features).
// out[M,N] = x[M,K] @ dequant(qweight)[K,N] + bias
// CTA 128x128x32, 8 warps (2M x 4N), warp tile 64x32.
// A: cp.async 4-stage ring. B: LDG int4-words -> dequant -> tf32 -> STS, 2-stage.

#define BM 128
#define BN 128
#define BK 32
#define AST 36              // A smem row stride (floats) -> conflict-free frags
#define BSTR 136            // B smem k-row stride (floats) -> conflict-free frags
#define ASTAGE 4608         // 128*36 floats per A stage
#define BSTAGE 4352         // 32*136 floats per B stage
#define SMEM_FLOATS (4 * ASTAGE + 2 * BSTAGE)
#define SMEM_BYTES (SMEM_FLOATS * 4)

#define CP_ASYNC8(dst, src) \
    asm volatile("cp.async.ca.shared.global [%0], [%1], 8;" :: "r"(dst), "l"(src))
#define CP_COMMIT() asm volatile("cp.async.commit_group;" ::: "memory")
#define CP_WAIT(N)  asm volatile("cp.async.wait_group %0;" :: "n"(N) : "memory")

__device__ __forceinline__ uint32_t f2tf32(float f) {
    uint32_t u;
    asm("cvt.rna.tf32.f32 %0, %1;" : "=r"(u) : "f"(f));
    return u;
}

__device__ __forceinline__ void mma_tf32(float& c0, float& c1, float& c2, float& c3,
                                         uint32_t a0, uint32_t a1, uint32_t a2, uint32_t a3,
                                         uint32_t b0, uint32_t b1) {
    asm volatile(
        "mma.sync.aligned.m16n8k8.row.col.f32.tf32.tf32.f32 "
        "{%0,%1,%2,%3}, {%4,%5,%6,%7}, {%8,%9}, {%0,%1,%2,%3};"
        : "+f"(c0), "+f"(c1), "+f"(c2), "+f"(c3)
        : "r"(a0), "r"(a1), "r"(a2), "r"(a3), "r"(b0), "r"(b1));
}

__global__ __launch_bounds__(256, 1)
void wq4_mma_kernel(const float* __restrict__ x,
                    const int*   __restrict__ qw,
                    const int*   __restrict__ zeros,
                    const float* __restrict__ scales,
                    const float* __restrict__ bias,
                    float* __restrict__ out,
                    int M, int K, int N)
{
    extern __shared__ float sm[];
    float* As = sm;                    // 4 stages of [128][36]
    float* Bs = sm + 4 * ASTAGE;       // 2 stages of [32][136]

    const int tid  = threadIdx.x;
    const int wid  = tid >> 5;
    const int lane = tid & 31;
    const int g    = lane >> 2;        // group id within warp (0..7)
    const int t    = lane & 3;         // thread in group (0..3)

    const int n0 = blockIdx.x * BN;
    const int m0 = blockIdx.y * BM;
    const int nq = N >> 3;
    const int NT = K / BK;             // 128

    const int mwarp = (wid & 1) * 64;
    const int nwarp = (wid >> 1) * 32;

    // ---- A cp.async mapping: 8 chunks of 8B per thread per stage ----
    // chunk c = i*256 + tid; row = c>>4 (16 chunks/row), kc = c&15
    const int arow0 = tid >> 4;        // rows arow0 + i*16
    const int akc   = tid & 15;
    const float* xA = x + (size_t)(m0 + arow0) * K + akc * 2;

    // ---- B mapping: kq = tid>>3 (k row), nb = tid&7 (16 n per thread) ----
    const int kq = tid >> 3;
    const int nb = tid & 7;
    const int* qP = qw + (size_t)kq * nq + (n0 >> 3) + nb * 2;
    const int sidx = n0 + nb * 16;     // base n for this thread's scales/zeros

    // group scale / (2^23 + zero) registers (16 n each)
    float s_r[16], c_r[16];
    float4 szT[4]; int4 zzT[4];

    // acc[mt][nt][4]
    float acc[4][4][4];
#pragma unroll
    for (int i = 0; i < 4; i++)
#pragma unroll
        for (int j = 0; j < 4; j++)
#pragma unroll
            for (int r = 0; r < 4; r++) acc[i][j][r] = 0.f;

    // ---- prologue: group 0 s/z ----
    {
        const float* sp = scales + sidx;
        const int*   zp = zeros  + sidx;
#pragma unroll
        for (int v = 0; v < 4; v++) {
            float4 s4 = ((const float4*)sp)[v];
            int4   z4 = ((const int4*)zp)[v];
            s_r[4*v+0] = s4.x; s_r[4*v+1] = s4.y; s_r[4*v+2] = s4.z; s_r[4*v+3] = s4.w;
            c_r[4*v+0] = __uint_as_float(0x4B000000u | (uint32_t)z4.x);
            c_r[4*v+1] = __uint_as_float(0x4B000000u | (uint32_t)z4.y);
            c_r[4*v+2] = __uint_as_float(0x4B000000u | (uint32_t)z4.z);
            c_r[4*v+3] = __uint_as_float(0x4B000000u | (uint32_t)z4.w);
        }
    }

    // issue A tiles 0 and 1
#pragma unroll
    for (int s = 0; s < 2; s++) {
#pragma unroll
        for (int i = 0; i < 8; i++) {
            const int row = arow0 + i * 16;
            uint32_t dst = (uint32_t)__cvta_generic_to_shared(
                &As[s * ASTAGE + row * AST + akc * 2]);
            CP_ASYNC8(dst, xA + (size_t)row * 0 /*row already in xA*/
                             + (size_t)(i * 16) * K + (size_t)s * BK);
        }
        CP_COMMIT();
    }

    // B tile 0 regs
    int2 breg = *(const int2*)(qP);
    int2 bnext;

    for (int kt = 0; kt < NT; kt++) {
        const int sA = kt & 3;
        const int sB = kt & 1;
        float* Bst = Bs + sB * BSTAGE;

        // ---- prefetch ----
        if (kt < NT - 2) {
            const size_t ko = (size_t)(kt + 2) * BK;
#pragma unroll
            for (int i = 0; i < 8; i++) {
                const int row = arow0 + i * 16;
                uint32_t dst = (uint32_t)__cvta_generic_to_shared(
                    &As[((kt + 2) & 3) * ASTAGE + row * AST + akc * 2]);
                CP_ASYNC8(dst, xA + (size_t)(i * 16) * K + ko);
            }
            CP_COMMIT();
        }
        if (kt < NT - 1) {
            bnext = *(const int2*)(qP + (size_t)(kt + 1) * BK * nq);
            if (((kt + 1) & 3) == 0) {
                const int grp = (kt + 1) >> 2;
                const float* sp = scales + (size_t)grp * N + sidx;
                const int*   zp = zeros  + (size_t)grp * N + sidx;
#pragma unroll
                for (int v = 0; v < 4; v++) {
                    szT[v] = ((const float4*)sp)[v];
                    zzT[v] = ((const int4*)zp)[v];
                }
            }
        }

        // ---- wait A(kt) ----
        if (kt < NT - 2)      { CP_WAIT(2); }
        else if (kt == NT - 2){ CP_WAIT(1); }
        else                  { CP_WAIT(0); }

        // ---- group boundary: commit prefetched s/z ----
        if (kt && ((kt & 3) == 0)) {
#pragma unroll
            for (int v = 0; v < 4; v++) {
                s_r[4*v+0] = szT[v].x; s_r[4*v+1] = szT[v].y;
                s_r[4*v+2] = szT[v].z; s_r[4*v+3] = szT[v].w;
                c_r[4*v+0] = __uint_as_float(0x4B000000u | (uint32_t)zzT[v].x);
                c_r[4*v+1] = __uint_as_float(0x4B000000u | (uint32_t)zzT[v].y);
                c_r[4*v+2] = __uint_as_float(0x4B000000u | (uint32_t)zzT[v].z);
                c_r[4*v+3] = __uint_as_float(0x4B000000u | (uint32_t)zzT[v].w);
            }
        }

        // ---- dequant B(kt) -> tf32 -> smem ----
        {
            const uint32_t w0 = (uint32_t)breg.x, w1 = (uint32_t)breg.y;
            float* dst = Bst + kq * BSTR + nb * 16;
            uint32_t tv[16];
#pragma unroll
            for (int j = 0; j < 8; j++) {
                float f0 = __uint_as_float(0x4B000000u | ((w0 >> (4 * j)) & 0xFu));
                float f1 = __uint_as_float(0x4B000000u | ((w1 >> (4 * j)) & 0xFu));
                tv[j]     = f2tf32((f0 - c_r[j])     * s_r[j]);
                tv[8 + j] = f2tf32((f1 - c_r[8 + j]) * s_r[8 + j]);
            }
#pragma unroll
            for (int j = 0; j < 16; j += 4) {
                *(float4*)(dst + j) = make_float4(
                    __uint_as_float(tv[j]),   __uint_as_float(tv[j+1]),
                    __uint_as_float(tv[j+2]), __uint_as_float(tv[j+3]));
            }
        }

        __syncthreads();

        // ---- compute: 4 k-steps of m16n8k8 ----
        const float* Ast = As + sA * ASTAGE;
#pragma unroll
        for (int ks = 0; ks < 4; ks++) {
            uint32_t aF[4][4];
#pragma unroll
            for (int mt = 0; mt < 4; mt++) {
                const float* ap = Ast + (mwarp + mt * 16 + g) * AST + ks * 8 + t;
                aF[mt][0] = f2tf32(ap[0]);
                aF[mt][1] = f2tf32(ap[8 * AST]);
                aF[mt][2] = f2tf32(ap[4]);
                aF[mt][3] = f2tf32(ap[8 * AST + 4]);
            }
            uint32_t bF[4][2];
#pragma unroll
            for (int nt = 0; nt < 4; nt++) {
                const float* bp = Bst + (ks * 8 + t) * BSTR + nwarp + nt * 8 + g;
                bF[nt][0] = __float_as_uint(bp[0]);
                bF[nt][1] = __float_as_uint(bp[4 * BSTR]);
            }
#pragma unroll
            for (int mt = 0; mt < 4; mt++)
#pragma unroll
                for (int nt = 0; nt < 4; nt++)
                    mma_tf32(acc[mt][nt][0], acc[mt][nt][1],
                             acc[mt][nt][2], acc[mt][nt][3],
                             aF[mt][0], aF[mt][1], aF[mt][2], aF[mt][3],
                             bF[nt][0], bF[nt][1]);
        }

        __syncthreads();
        breg = bnext;
    }

    // ---- epilogue: bias + store ----
#pragma unroll
    for (int nt = 0; nt < 4; nt++) {
        const int col = n0 + nwarp + nt * 8 + 2 * t;
        const float2 bb = *(const float2*)(bias + col);
#pragma unroll
        for (int mt = 0; mt < 4; mt++) {
            const int row0 = m0 + mwarp + mt * 16 + g;
            *(float2*)(out + (size_t)row0 * N + col) =
                make_float2(acc[mt][nt][0] + bb.x, acc[mt][nt][1] + bb.y);
            *(float2*)(out + (size_t)(row0 + 8) * N + col) =
                make_float2(acc[mt][nt][2] + bb.x, acc[mt][nt][3] + bb.y);
        }
    }
}

extern "C" void kernel_launch(void* const* d_in, const int* in_sizes, int n_in,
                              void* d_out, int out_size)
{
    const float* x      = (const float*)d_in[0];
    const int*   qw     = (const int*)d_in[1];
    const int*   zeros  = (const int*)d_in[2];
    const float* scales = (const float*)d_in[3];
    const float* bias   = (const float*)d_in[4];
    float* out = (float*)d_out;

    const int N = in_sizes[4];                                   // 11008
    const int K = (int)(((long long)in_sizes[1] * 8) / N);       // 4096
    const int M = in_sizes[0] / K;                               // 4096

    cudaFuncSetAttribute(wq4_mma_kernel,
                         cudaFuncAttributeMaxDynamicSharedMemorySize, SMEM_BYTES);

    dim3 grid(N / BN, M / BM);
    wq4_mma_kernel<<<grid, 256, SMEM_BYTES>>>(x, qw, zeros, scales, bias, out, M, K, N);
}

// round 4
// speedup vs baseline: 2.5360x; 1.2515x over previous
#include <cuda_runtime.h>
#include <cstdint>

// W4 group-quant GEMM via mma.sync.m16n8k8.tf32 (base sm_103 PTX target).
// out[M,N] = x[M,K] @ dequant(qweight)[K,N] + bias
// R4: 512 threads / 16 warps (4M x 4N), warp tile 32x32, single sync/tile,
// 4-stage cp.async A ring, 2-stage B dequant buffer.

#define BM 128
#define BN 128
#define BK 32
#define AST 36               // A smem row stride (floats): frag LDS conflict-free
#define BSTR 136             // B smem k-row stride (floats): frag LDS conflict-free
#define ASTAGE 4608          // 128*36 floats
#define BSTAGE 4352          // 32*136 floats
#define SMEM_FLOATS (4 * ASTAGE + 2 * BSTAGE)
#define SMEM_BYTES (SMEM_FLOATS * 4)   // 108544

#define CP_ASYNC16(dst, src) \
    asm volatile("cp.async.ca.shared.global [%0], [%1], 16;" :: "r"(dst), "l"(src))
#define CP_COMMIT() asm volatile("cp.async.commit_group;" ::: "memory")
#define CP_WAIT(N)  asm volatile("cp.async.wait_group %0;" :: "n"(N) : "memory")

__device__ __forceinline__ uint32_t f2tf32(float f) {
    uint32_t u;
    asm("cvt.rna.tf32.f32 %0, %1;" : "=r"(u) : "f"(f));
    return u;
}

__device__ __forceinline__ void mma_tf32(float& c0, float& c1, float& c2, float& c3,
                                         uint32_t a0, uint32_t a1, uint32_t a2, uint32_t a3,
                                         uint32_t b0, uint32_t b1) {
    asm volatile(
        "mma.sync.aligned.m16n8k8.row.col.f32.tf32.tf32.f32 "
        "{%0,%1,%2,%3}, {%4,%5,%6,%7}, {%8,%9}, {%0,%1,%2,%3};"
        : "+f"(c0), "+f"(c1), "+f"(c2), "+f"(c3)
        : "r"(a0), "r"(a1), "r"(a2), "r"(a3), "r"(b0), "r"(b1));
}

__global__ __launch_bounds__(512, 1)
void wq4_mma_kernel(const float* __restrict__ x,
                    const int*   __restrict__ qw,
                    const int*   __restrict__ zeros,
                    const float* __restrict__ scales,
                    const float* __restrict__ bias,
                    float* __restrict__ out,
                    int M, int K, int N)
{
    extern __shared__ float sm[];
    float* As = sm;                    // 4 stages [128][36]
    float* Bs = sm + 4 * ASTAGE;       // 2 stages [32][136]

    const int tid  = threadIdx.x;
    const int wid  = tid >> 5;
    const int lane = tid & 31;
    const int g    = lane >> 2;
    const int t    = lane & 3;

    const int n0 = blockIdx.x * BN;
    const int m0 = blockIdx.y * BM;
    const int nq = N >> 3;
    const int NT = K / BK;             // 128

    const int mwarp = (wid & 3) * 32;
    const int nwarp = (wid >> 2) * 32;

    // ---- A cp.async mapping: 2 x 16B per thread per stage ----
    const int arow0 = tid >> 3;        // rows arow0, arow0+64
    const int ac4   = tid & 7;         // float4 index within row
    const float* xA = x + (size_t)(m0 + arow0) * K + ac4 * 4;

    // ---- B mapping: k-row = tid>>4, word = tid&15 (8 n each) ----
    const int bk = tid >> 4;
    const int bw = tid & 15;
    const int* qP = qw + (size_t)bk * nq + (n0 >> 3) + bw;
    const int sidx = n0 + bw * 8;
    float* bDst0 = Bs + bk * BSTR + bw * 8;

    // group scale / (2^23+zero) for this thread's 8 n-values
    float s_r[8], c_r[8];
    float4 szT[2]; int4 zzT[2];

    float acc[2][4][4];
#pragma unroll
    for (int i = 0; i < 2; i++)
#pragma unroll
        for (int j = 0; j < 4; j++)
#pragma unroll
            for (int r = 0; r < 4; r++) acc[i][j][r] = 0.f;

    // group 0 s/z
    {
        const float4 s0 = ((const float4*)(scales + sidx))[0];
        const float4 s1 = ((const float4*)(scales + sidx))[1];
        const int4   z0 = ((const int4*)(zeros + sidx))[0];
        const int4   z1 = ((const int4*)(zeros + sidx))[1];
        s_r[0]=s0.x; s_r[1]=s0.y; s_r[2]=s0.z; s_r[3]=s0.w;
        s_r[4]=s1.x; s_r[5]=s1.y; s_r[6]=s1.z; s_r[7]=s1.w;
        c_r[0]=__uint_as_float(0x4B000000u|(uint32_t)z0.x);
        c_r[1]=__uint_as_float(0x4B000000u|(uint32_t)z0.y);
        c_r[2]=__uint_as_float(0x4B000000u|(uint32_t)z0.z);
        c_r[3]=__uint_as_float(0x4B000000u|(uint32_t)z0.w);
        c_r[4]=__uint_as_float(0x4B000000u|(uint32_t)z1.x);
        c_r[5]=__uint_as_float(0x4B000000u|(uint32_t)z1.y);
        c_r[6]=__uint_as_float(0x4B000000u|(uint32_t)z1.z);
        c_r[7]=__uint_as_float(0x4B000000u|(uint32_t)z1.w);
    }

    // issue A tiles 0,1
#pragma unroll
    for (int s = 0; s < 2; s++) {
#pragma unroll
        for (int i = 0; i < 2; i++) {
            uint32_t dst = (uint32_t)__cvta_generic_to_shared(
                &As[s * ASTAGE + (arow0 + i * 64) * AST + ac4 * 4]);
            CP_ASYNC16(dst, xA + (size_t)(i * 64) * K + (size_t)s * BK);
        }
        CP_COMMIT();
    }

    int breg = *qP;
    int bnext = 0;

    for (int kt = 0; kt < NT; kt++) {
        // ---- prefetch A(kt+2), B(kt+1), group s/z ----
        if (kt < NT - 2) {
            const size_t ko = (size_t)(kt + 2) * BK;
            float* stg = As + ((kt + 2) & 3) * ASTAGE;
#pragma unroll
            for (int i = 0; i < 2; i++) {
                uint32_t dst = (uint32_t)__cvta_generic_to_shared(
                    &stg[(arow0 + i * 64) * AST + ac4 * 4]);
                CP_ASYNC16(dst, xA + (size_t)(i * 64) * K + ko);
            }
            CP_COMMIT();
        }
        if (kt < NT - 1) {
            bnext = qP[(size_t)(kt + 1) * BK * nq];
            if (((kt + 1) & 3) == 0) {
                const int grp = (kt + 1) >> 2;
                szT[0] = ((const float4*)(scales + (size_t)grp * N + sidx))[0];
                szT[1] = ((const float4*)(scales + (size_t)grp * N + sidx))[1];
                zzT[0] = ((const int4*)(zeros + (size_t)grp * N + sidx))[0];
                zzT[1] = ((const int4*)(zeros + (size_t)grp * N + sidx))[1];
            }
        }

        if (kt < NT - 2)       { CP_WAIT(2); }
        else if (kt == NT - 2) { CP_WAIT(1); }
        else                   { CP_WAIT(0); }

        if (kt && ((kt & 3) == 0)) {
            s_r[0]=szT[0].x; s_r[1]=szT[0].y; s_r[2]=szT[0].z; s_r[3]=szT[0].w;
            s_r[4]=szT[1].x; s_r[5]=szT[1].y; s_r[6]=szT[1].z; s_r[7]=szT[1].w;
            c_r[0]=__uint_as_float(0x4B000000u|(uint32_t)zzT[0].x);
            c_r[1]=__uint_as_float(0x4B000000u|(uint32_t)zzT[0].y);
            c_r[2]=__uint_as_float(0x4B000000u|(uint32_t)zzT[0].z);
            c_r[3]=__uint_as_float(0x4B000000u|(uint32_t)zzT[0].w);
            c_r[4]=__uint_as_float(0x4B000000u|(uint32_t)zzT[1].x);
            c_r[5]=__uint_as_float(0x4B000000u|(uint32_t)zzT[1].y);
            c_r[6]=__uint_as_float(0x4B000000u|(uint32_t)zzT[1].z);
            c_r[7]=__uint_as_float(0x4B000000u|(uint32_t)zzT[1].w);
        }

        // ---- dequant B(kt) -> tf32 -> smem ----
        {
            const uint32_t w = (uint32_t)breg;
            float* dst = bDst0 + (kt & 1) * BSTAGE;
            uint32_t tv[8];
#pragma unroll
            for (int j = 0; j < 8; j++) {
                float f = __uint_as_float(0x4B000000u | ((w >> (4 * j)) & 0xFu));
                tv[j] = f2tf32((f - c_r[j]) * s_r[j]);
            }
            *(float4*)(dst)     = make_float4(__uint_as_float(tv[0]), __uint_as_float(tv[1]),
                                              __uint_as_float(tv[2]), __uint_as_float(tv[3]));
            *(float4*)(dst + 4) = make_float4(__uint_as_float(tv[4]), __uint_as_float(tv[5]),
                                              __uint_as_float(tv[6]), __uint_as_float(tv[7]));
        }

        __syncthreads();

        // ---- compute: 4 k-steps ----
        const float* Ast = As + (kt & 3) * ASTAGE;
        const float* Bst = Bs + (kt & 1) * BSTAGE;
#pragma unroll
        for (int ks = 0; ks < 4; ks++) {
            uint32_t aF[2][4];
#pragma unroll
            for (int mt = 0; mt < 2; mt++) {
                const float* ap = Ast + (mwarp + mt * 16 + g) * AST + ks * 8 + t;
                aF[mt][0] = f2tf32(ap[0]);
                aF[mt][1] = f2tf32(ap[8 * AST]);
                aF[mt][2] = f2tf32(ap[4]);
                aF[mt][3] = f2tf32(ap[8 * AST + 4]);
            }
            uint32_t bF[4][2];
#pragma unroll
            for (int nt = 0; nt < 4; nt++) {
                const float* bp = Bst + (ks * 8 + t) * BSTR + nwarp + nt * 8 + g;
                bF[nt][0] = __float_as_uint(bp[0]);
                bF[nt][1] = __float_as_uint(bp[4 * BSTR]);
            }
#pragma unroll
            for (int mt = 0; mt < 2; mt++)
#pragma unroll
                for (int nt = 0; nt < 4; nt++)
                    mma_tf32(acc[mt][nt][0], acc[mt][nt][1],
                             acc[mt][nt][2], acc[mt][nt][3],
                             aF[mt][0], aF[mt][1], aF[mt][2], aF[mt][3],
                             bF[nt][0], bF[nt][1]);
        }

        breg = bnext;
    }

    // ---- epilogue ----
#pragma unroll
    for (int nt = 0; nt < 4; nt++) {
        const int col = n0 + nwarp + nt * 8 + 2 * t;
        const float2 bb = *(const float2*)(bias + col);
#pragma unroll
        for (int mt = 0; mt < 2; mt++) {
            const int row0 = m0 + mwarp + mt * 16 + g;
            *(float2*)(out + (size_t)row0 * N + col) =
                make_float2(acc[mt][nt][0] + bb.x, acc[mt][nt][1] + bb.y);
            *(float2*)(out + (size_t)(row0 + 8) * N + col) =
                make_float2(acc[mt][nt][2] + bb.x, acc[mt][nt][3] + bb.y);
        }
    }
}

extern "C" void kernel_launch(void* const* d_in, const int* in_sizes, int n_in,
                              void* d_out, int out_size)
{
    const float* x      = (const float*)d_in[0];
    const int*   qw     = (const int*)d_in[1];
    const int*   zeros  = (const int*)d_in[2];
    const float* scales = (const float*)d_in[3];
    const float* bias   = (const float*)d_in[4];
    float* out = (float*)d_out;

    const int N = in_sizes[4];                                   // 11008
    const int K = (int)(((long long)in_sizes[1] * 8) / N);       // 4096
    const int M = in_sizes[0] / K;                               // 4096

    cudaFuncSetAttribute(wq4_mma_kernel,
                         cudaFuncAttributeMaxDynamicSharedMemorySize, SMEM_BYTES);

    dim3 grid(N / BN, M / BM);
    wq4_mma_kernel<<<grid, 512, SMEM_BYTES>>>(x, qw, zeros, scales, bias, out, M, K, N);
}

// round 5
// speedup vs baseline: 2.6898x; 1.0607x over previous
#include <cuda_runtime.h>
#include <cstdint>

// W4 group-quant GEMM via mma.sync.m16n8k8.tf32 (base sm_103 PTX target).
// R5: two kernels.
//  1) prep: x[M,K] fp32 -> tf32(rna) in MMA-fragment-order scratch
//     (slab = 16m x 8k = 128 floats = [lane(32)][a0,a1,a2,a3])
//  2) gemm: A via cp.async from scratch (consumer: 1 LDS.128 per fragment,
//     no cvt), B dequant int4->tf32 on the fly as before.

#define BM 128
#define BN 128
#define BK 32
#define ASTAGE 4096          // floats per A stage (128x32, fragment order)
#define BSTR 136             // B smem k-row stride (floats)
#define BSTAGE 4352          // 32*136
#define SMEM_FLOATS (4 * ASTAGE + 2 * BSTAGE)
#define SMEM_BYTES (SMEM_FLOATS * 4)     // 100352

#define MAX_MK (4096 * 4096)
__device__ float g_xfrag[MAX_MK];        // static scratch (no allocs allowed)

#define CP_ASYNC16(dst, src) \
    asm volatile("cp.async.ca.shared.global [%0], [%1], 16;" :: "r"(dst), "l"(src))
#define CP_COMMIT() asm volatile("cp.async.commit_group;" ::: "memory")
#define CP_WAIT(N)  asm volatile("cp.async.wait_group %0;" :: "n"(N) : "memory")

__device__ __forceinline__ uint32_t f2tf32(float f) {
    uint32_t u;
    asm("cvt.rna.tf32.f32 %0, %1;" : "=r"(u) : "f"(f));
    return u;
}

__device__ __forceinline__ void mma_tf32(float& c0, float& c1, float& c2, float& c3,
                                         uint32_t a0, uint32_t a1, uint32_t a2, uint32_t a3,
                                         uint32_t b0, uint32_t b1) {
    asm volatile(
        "mma.sync.aligned.m16n8k8.row.col.f32.tf32.tf32.f32 "
        "{%0,%1,%2,%3}, {%4,%5,%6,%7}, {%8,%9}, {%0,%1,%2,%3};"
        : "+f"(c0), "+f"(c1), "+f"(c2), "+f"(c3)
        : "r"(a0), "r"(a1), "r"(a2), "r"(a3), "r"(b0), "r"(b1));
}

// ---- prep: one warp per slab (16m x 8k). lane l -> g=l>>2, t=l&3.
// slot order per lane: (g,t), (g+8,t), (g,t+4), (g+8,t+4)
__global__ __launch_bounds__(128)
void xprep_kernel(const float* __restrict__ x, int M, int K)
{
    const int KB = K >> 3;
    const int slab = blockIdx.x * 4 + (threadIdx.x >> 5);
    const int lane = threadIdx.x & 31;
    const int mB = slab / KB;
    const int kB = slab - mB * KB;
    const int g = lane >> 2;
    const int t = lane & 3;
    const float* src = x + (size_t)(mB * 16 + g) * K + kB * 8 + t;
    float4 v;
    v.x = __uint_as_float(f2tf32(src[0]));
    v.y = __uint_as_float(f2tf32(src[(size_t)8 * K]));
    v.z = __uint_as_float(f2tf32(src[4]));
    v.w = __uint_as_float(f2tf32(src[(size_t)8 * K + 4]));
    *(float4*)(g_xfrag + (size_t)slab * 128 + lane * 4) = v;
}

__global__ __launch_bounds__(512, 1)
void wq4_mma_kernel(const int*   __restrict__ qw,
                    const int*   __restrict__ zeros,
                    const float* __restrict__ scales,
                    const float* __restrict__ bias,
                    float* __restrict__ out,
                    int M, int K, int N)
{
    extern __shared__ float sm[];
    float* As = sm;                    // 4 stages x 4096 floats (fragment order)
    float* Bs = sm + 4 * ASTAGE;       // 2 stages [32][136]

    const int tid  = threadIdx.x;
    const int wid  = tid >> 5;
    const int lane = tid & 31;
    const int g    = lane >> 2;
    const int t    = lane & 3;

    const int n0 = blockIdx.x * BN;
    const int m0 = blockIdx.y * BM;
    const int nq = N >> 3;
    const int KB = K >> 3;
    const int NT = K / BK;             // 128

    const int mwarp = (wid & 3) * 32;  // 2 m-slabs per warp
    const int nwarp = (wid >> 2) * 32;
    const int mS0 = mwarp >> 4;        // first m-slab index (0..7) within tile

    // ---- A cp.async mapping: 2 x 16B chunks per thread per stage ----
    // chunk c: slab s = c>>5 (mS = s>>2, kS = s&3), part = c&31
    const int mB0 = m0 >> 4;
    const float* aSrc0;
    const float* aSrc1;
    {
        const int c0 = tid, c1 = tid + 512;
        const int s0 = c0 >> 5, s1 = c1 >> 5;
        aSrc0 = g_xfrag + ((size_t)(mB0 + (s0 >> 2)) * KB + (s0 & 3)) * 128 + (c0 & 31) * 4;
        aSrc1 = g_xfrag + ((size_t)(mB0 + (s1 >> 2)) * KB + (s1 & 3)) * 128 + (c1 & 31) * 4;
    }
    // per k-tile, source advances by 4 slabs = 512 floats
    const uint32_t aDst0 = (uint32_t)__cvta_generic_to_shared(As) + (uint32_t)tid * 16;
    const uint32_t aDst1 = aDst0 + 512 * 16;

    // ---- B mapping: k-row = tid>>4, word = tid&15 (8 n each) ----
    const int bk = tid >> 4;
    const int bw = tid & 15;
    const int* qP = qw + (size_t)bk * nq + (n0 >> 3) + bw;
    const int sidx = n0 + bw * 8;
    float* bDst0 = Bs + bk * BSTR + bw * 8;

    float s_r[8], c_r[8];
    float4 szT[2]; int4 zzT[2];

    float acc[2][4][4];
#pragma unroll
    for (int i = 0; i < 2; i++)
#pragma unroll
        for (int j = 0; j < 4; j++)
#pragma unroll
            for (int r = 0; r < 4; r++) acc[i][j][r] = 0.f;

    // group 0 s/z
    {
        const float4 s0 = ((const float4*)(scales + sidx))[0];
        const float4 s1 = ((const float4*)(scales + sidx))[1];
        const int4   z0 = ((const int4*)(zeros + sidx))[0];
        const int4   z1 = ((const int4*)(zeros + sidx))[1];
        s_r[0]=s0.x; s_r[1]=s0.y; s_r[2]=s0.z; s_r[3]=s0.w;
        s_r[4]=s1.x; s_r[5]=s1.y; s_r[6]=s1.z; s_r[7]=s1.w;
        c_r[0]=__uint_as_float(0x4B000000u|(uint32_t)z0.x);
        c_r[1]=__uint_as_float(0x4B000000u|(uint32_t)z0.y);
        c_r[2]=__uint_as_float(0x4B000000u|(uint32_t)z0.z);
        c_r[3]=__uint_as_float(0x4B000000u|(uint32_t)z0.w);
        c_r[4]=__uint_as_float(0x4B000000u|(uint32_t)z1.x);
        c_r[5]=__uint_as_float(0x4B000000u|(uint32_t)z1.y);
        c_r[6]=__uint_as_float(0x4B000000u|(uint32_t)z1.z);
        c_r[7]=__uint_as_float(0x4B000000u|(uint32_t)z1.w);
    }

    // issue A tiles 0,1  (per tile: +4 slabs = +512 floats in scratch)
#pragma unroll
    for (int s = 0; s < 2; s++) {
        CP_ASYNC16(aDst0 + (uint32_t)s * (ASTAGE * 4), aSrc0 + (size_t)s * 512);
        CP_ASYNC16(aDst1 + (uint32_t)s * (ASTAGE * 4), aSrc1 + (size_t)s * 512);
        CP_COMMIT();
    }

    int breg = *qP;
    int bnext = 0;

    for (int kt = 0; kt < NT; kt++) {
        // ---- prefetch A(kt+2), B(kt+1), group s/z ----
        if (kt < NT - 2) {
            const uint32_t so = (uint32_t)((kt + 2) & 3) * (ASTAGE * 4);
            const size_t go = (size_t)(kt + 2) * 512;
            CP_ASYNC16(aDst0 + so, aSrc0 + go);
            CP_ASYNC16(aDst1 + so, aSrc1 + go);
            CP_COMMIT();
        }
        if (kt < NT - 1) {
            bnext = qP[(size_t)(kt + 1) * BK * nq];
            if (((kt + 1) & 3) == 0) {
                const int grp = (kt + 1) >> 2;
                szT[0] = ((const float4*)(scales + (size_t)grp * N + sidx))[0];
                szT[1] = ((const float4*)(scales + (size_t)grp * N + sidx))[1];
                zzT[0] = ((const int4*)(zeros + (size_t)grp * N + sidx))[0];
                zzT[1] = ((const int4*)(zeros + (size_t)grp * N + sidx))[1];
            }
        }

        if (kt < NT - 2)       { CP_WAIT(2); }
        else if (kt == NT - 2) { CP_WAIT(1); }
        else                   { CP_WAIT(0); }

        if (kt && ((kt & 3) == 0)) {
            s_r[0]=szT[0].x; s_r[1]=szT[0].y; s_r[2]=szT[0].z; s_r[3]=szT[0].w;
            s_r[4]=szT[1].x; s_r[5]=szT[1].y; s_r[6]=szT[1].z; s_r[7]=szT[1].w;
            c_r[0]=__uint_as_float(0x4B000000u|(uint32_t)zzT[0].x);
            c_r[1]=__uint_as_float(0x4B000000u|(uint32_t)zzT[0].y);
            c_r[2]=__uint_as_float(0x4B000000u|(uint32_t)zzT[0].z);
            c_r[3]=__uint_as_float(0x4B000000u|(uint32_t)zzT[0].w);
            c_r[4]=__uint_as_float(0x4B000000u|(uint32_t)zzT[1].x);
            c_r[5]=__uint_as_float(0x4B000000u|(uint32_t)zzT[1].y);
            c_r[6]=__uint_as_float(0x4B000000u|(uint32_t)zzT[1].z);
            c_r[7]=__uint_as_float(0x4B000000u|(uint32_t)zzT[1].w);
        }

        // ---- dequant B(kt) -> tf32 -> smem ----
        {
            const uint32_t w = (uint32_t)breg;
            float* dst = bDst0 + (kt & 1) * BSTAGE;
            uint32_t tv[8];
#pragma unroll
            for (int j = 0; j < 8; j++) {
                float f = __uint_as_float(0x4B000000u | ((w >> (4 * j)) & 0xFu));
                tv[j] = f2tf32((f - c_r[j]) * s_r[j]);
            }
            *(float4*)(dst)     = make_float4(__uint_as_float(tv[0]), __uint_as_float(tv[1]),
                                              __uint_as_float(tv[2]), __uint_as_float(tv[3]));
            *(float4*)(dst + 4) = make_float4(__uint_as_float(tv[4]), __uint_as_float(tv[5]),
                                              __uint_as_float(tv[6]), __uint_as_float(tv[7]));
        }

        __syncthreads();

        // ---- compute: 4 k-steps; A fragments = 1 LDS.128 each ----
        const float* Ast = As + (kt & 3) * ASTAGE;
        const float* Bst = Bs + (kt & 1) * BSTAGE;
#pragma unroll
        for (int ks = 0; ks < 4; ks++) {
            uint32_t aF[2][4];
#pragma unroll
            for (int mt = 0; mt < 2; mt++) {
                const float4 v = *(const float4*)(Ast + ((mS0 + mt) * 4 + ks) * 128 + lane * 4);
                aF[mt][0] = __float_as_uint(v.x);
                aF[mt][1] = __float_as_uint(v.y);
                aF[mt][2] = __float_as_uint(v.z);
                aF[mt][3] = __float_as_uint(v.w);
            }
            uint32_t bF[4][2];
#pragma unroll
            for (int nt = 0; nt < 4; nt++) {
                const float* bp = Bst + (ks * 8 + t) * BSTR + nwarp + nt * 8 + g;
                bF[nt][0] = __float_as_uint(bp[0]);
                bF[nt][1] = __float_as_uint(bp[4 * BSTR]);
            }
#pragma unroll
            for (int mt = 0; mt < 2; mt++)
#pragma unroll
                for (int nt = 0; nt < 4; nt++)
                    mma_tf32(acc[mt][nt][0], acc[mt][nt][1],
                             acc[mt][nt][2], acc[mt][nt][3],
                             aF[mt][0], aF[mt][1], aF[mt][2], aF[mt][3],
                             bF[nt][0], bF[nt][1]);
        }

        breg = bnext;
    }

    // ---- epilogue ----
#pragma unroll
    for (int nt = 0; nt < 4; nt++) {
        const int col = n0 + nwarp + nt * 8 + 2 * t;
        const float2 bb = *(const float2*)(bias + col);
#pragma unroll
        for (int mt = 0; mt < 2; mt++) {
            const int row0 = m0 + mwarp + mt * 16 + g;
            *(float2*)(out + (size_t)row0 * N + col) =
                make_float2(acc[mt][nt][0] + bb.x, acc[mt][nt][1] + bb.y);
            *(float2*)(out + (size_t)(row0 + 8) * N + col) =
                make_float2(acc[mt][nt][2] + bb.x, acc[mt][nt][3] + bb.y);
        }
    }
}

extern "C" void kernel_launch(void* const* d_in, const int* in_sizes, int n_in,
                              void* d_out, int out_size)
{
    const float* x      = (const float*)d_in[0];
    const int*   qw     = (const int*)d_in[1];
    const int*   zeros  = (const int*)d_in[2];
    const float* scales = (const float*)d_in[3];
    const float* bias   = (const float*)d_in[4];
    float* out = (float*)d_out;

    const int N = in_sizes[4];                                   // 11008
    const int K = (int)(((long long)in_sizes[1] * 8) / N);       // 4096
    const int M = in_sizes[0] / K;                               // 4096

    // prep: x -> tf32 fragment-order scratch
    const int slabs = (M / 16) * (K / 8);
    xprep_kernel<<<slabs / 4, 128>>>(x, M, K);

    cudaFuncSetAttribute(wq4_mma_kernel,
                         cudaFuncAttributeMaxDynamicSharedMemorySize, SMEM_BYTES);
    dim3 grid(N / BN, M / BM);
    wq4_mma_kernel<<<grid, 512, SMEM_BYTES>>>(qw, zeros, scales, bias, out, M, K, N);
}

// round 8
// speedup vs baseline: 5.1785x; 1.9252x over previous
#include <cuda_runtime.h>
#include <cuda_fp16.h>
#include <cstdint>

// W4 group-quant GEMM via mma.sync.m16n8k16.f16 (fp32 accum), base sm_103 PTX.
// out[M,N] = x[M,K] @ dequant(qweight)[K,N] + bias
// R8: fix B-smem swizzle (confined XOR: pos = w*8 + (j ^ (w&4)); R7 used an
// ADD that made adjacent lanes' regions overlap -> corrupt B, rel_err 0.30).
// prep: x fp32 -> fp16 MMA-fragment order scratch (16m x 16k slabs).
// gemm: BM=128, BN=256, BK=32, 512 thr / 16 warps (4M x 4N), WM=32, WN=64.

#define THREADS 512
#define BM 128
#define BN 256
#define BK 32
#define BROW 264                     // B smem row stride (u32) per k-pair row
#define A_STG_U32 2048               // 8KB per A stage (16 slabs x 128 u32)
#define B_STG_U32 (16 * BROW)        // 4224 u32
#define TAB_OFF (4 * A_STG_U32 + 2 * B_STG_U32)   // 16640
#define SMEM_U32 (TAB_OFF + 1024)
#define SMEM_BYTES (SMEM_U32 * 4)    // 70656

#define MAX_MK (4096 * 4096)
__device__ uint32_t g_xa[MAX_MK / 2];   // x as fp16 fragments (32MB)

#define CP_ASYNC16(dst, src) \
    asm volatile("cp.async.ca.shared.global [%0], [%1], 16;" :: "r"(dst), "l"(src))
#define CP_COMMIT() asm volatile("cp.async.commit_group;" ::: "memory")
#define CP_WAIT(N)  asm volatile("cp.async.wait_group %0;" :: "n"(N) : "memory")

__device__ __forceinline__ uint32_t h2u(__half2 h) { return *reinterpret_cast<uint32_t*>(&h); }
__device__ __forceinline__ __half2 u2h(uint32_t u) { return *reinterpret_cast<__half2*>(&u); }

__device__ __forceinline__ void mma_f16(float& c0, float& c1, float& c2, float& c3,
                                        uint32_t a0, uint32_t a1, uint32_t a2, uint32_t a3,
                                        uint32_t b0, uint32_t b1) {
    asm volatile(
        "mma.sync.aligned.m16n8k16.row.col.f32.f16.f16.f32 "
        "{%0,%1,%2,%3}, {%4,%5,%6,%7}, {%8,%9}, {%0,%1,%2,%3};"
        : "+f"(c0), "+f"(c1), "+f"(c2), "+f"(c3)
        : "r"(a0), "r"(a1), "r"(a2), "r"(a3), "r"(b0), "r"(b1));
}

// ---- prep: warp per 16m x 16k slab. lane(g,t): a0=(g,2t..2t+1), a1=(g+8,..),
// a2=(g,2t+8..), a3=(g+8,2t+8..). fp32 -> fp16(rn).
__global__ __launch_bounds__(128)
void xprep_kernel(const float* __restrict__ x, int M, int K)
{
    const int KS = K >> 4;
    const int slab = blockIdx.x * 4 + (threadIdx.x >> 5);
    const int lane = threadIdx.x & 31;
    const int mB = slab / KS;
    const int kB = slab - mB * KS;
    const int g = lane >> 2, t = lane & 3;
    const float* src = x + (size_t)(mB * 16 + g) * K + kB * 16 + 2 * t;
    float2 p00 = *(const float2*)(src);
    float2 p10 = *(const float2*)(src + (size_t)8 * K);
    float2 p01 = *(const float2*)(src + 8);
    float2 p11 = *(const float2*)(src + (size_t)8 * K + 8);
    uint4 v;
    v.x = h2u(__float22half2_rn(p00));
    v.y = h2u(__float22half2_rn(p10));
    v.z = h2u(__float22half2_rn(p01));
    v.w = h2u(__float22half2_rn(p11));
    *(uint4*)(g_xa + (size_t)slab * 128 + lane * 4) = v;
}

__global__ __launch_bounds__(THREADS, 1)
void wq4_mma_kernel(const int*   __restrict__ qw,
                    const int*   __restrict__ zeros,
                    const float* __restrict__ scales,
                    const float* __restrict__ bias,
                    float* __restrict__ out,
                    int M, int K, int N)
{
    extern __shared__ uint32_t sm[];
    uint32_t* As = sm;                         // 4 stages x 2048 u32
    uint32_t* Bs = sm + 4 * A_STG_U32;         // 2 stages x 4224 u32
    uint32_t* tS = sm + TAB_OFF;               // [2][256] half2-dup scales (linear)
    uint32_t* tZ = tS + 512;                   // [2][256] half2 zero-points (linear)

    const int tid  = threadIdx.x;
    const int wid  = tid >> 5;
    const int lane = tid & 31;
    const int g    = lane >> 2;
    const int t    = lane & 3;

    const int n0 = blockIdx.x * BN;
    const int m0 = blockIdx.y * BM;
    const int nq = N >> 3;
    const int NT = K / BK;                     // 128
    const int NG = K >> 7;                     // 32 groups

    const int nwarp = (wid >> 2) * 64;

    // ---- A cp.async: 1 x 16B per thread per stage ----
    const int sL = tid >> 5, part = tid & 31;
    const int KSLAB = K >> 4;
    const uint32_t* aSrc = g_xa + ((size_t)((m0 >> 4) + (sL >> 1)) * KSLAB + (sL & 1)) * 128
                           + part * 4;
    const uint32_t aDst = (uint32_t)__cvta_generic_to_shared(As) + (uint32_t)tid * 16;

    // ---- B: kp = wid (k-pair row), w = lane (8 n each) ----
    const int kp = wid, w = lane;
    const int* qP = qw + (size_t)(2 * kp) * nq + (n0 >> 3) + w;
    const int wsw = w & 4;                     // XOR swizzle selector (0 or 4)
    uint32_t* bDst = Bs + kp * BROW + w * 8;   // base of this lane's 8-slot region

    float acc[2][8][4];
#pragma unroll
    for (int i = 0; i < 2; i++)
#pragma unroll
        for (int j = 0; j < 8; j++)
#pragma unroll
            for (int r = 0; r < 4; r++) acc[i][j][r] = 0.f;

    // ---- prologue: tables for groups 0,1 (linear: index = n-within-tile) ----
    if (tid < 256) {
#pragma unroll
        for (int gg = 0; gg < 2; gg++) {
            float s = scales[(size_t)gg * N + n0 + tid];
            int   z = zeros[(size_t)gg * N + n0 + tid];
            tS[gg * 256 + tid] = h2u(__half2half2(__float2half_rn(s)));
            tZ[gg * 256 + tid] = 0x64006400u | (uint32_t)z | ((uint32_t)z << 16);
        }
    }

    // issue A tiles 0,1
    CP_ASYNC16(aDst, aSrc);
    CP_COMMIT();
    CP_ASYNC16(aDst + A_STG_U32 * 4, aSrc + 256);
    CP_COMMIT();

    __syncthreads();   // tables visible

    int breg0 = qP[0], breg1 = qP[nq];
    int bn0 = 0, bn1 = 0;
    float sf_next = 0.f; int zi_next = 0;
    uint32_t s2[8], zp2[8];

    for (int kt = 0; kt < NT; kt++) {
        // ---- prefetch A(kt+2), B(kt+1), table LDG ----
        if (kt < NT - 2) {
            CP_ASYNC16(aDst + (uint32_t)((kt + 2) & 3) * (A_STG_U32 * 4),
                       aSrc + (size_t)(kt + 2) * 256);
            CP_COMMIT();
        }
        if (kt < NT - 1) {
            const int* qn = qP + (size_t)(kt + 1) * 32 * nq;
            bn0 = qn[0]; bn1 = qn[nq];
        }
        if ((kt & 3) == 2 && tid < 256) {
            const int gL = (kt >> 2) + 2;
            if (gL < NG) {
                sf_next = scales[(size_t)gL * N + n0 + tid];
                zi_next = zeros[(size_t)gL * N + n0 + tid];
            }
        }

        if (kt < NT - 2)       { CP_WAIT(2); }
        else if (kt == NT - 2) { CP_WAIT(1); }
        else                   { CP_WAIT(0); }

        if ((kt & 3) == 0) {
            const int gC = kt >> 2;
            const int tb = (gC & 1) * 256 + w * 8;
            uint4 sA = *(uint4*)(tS + tb); uint4 sB = *(uint4*)(tS + tb + 4);
            uint4 zA = *(uint4*)(tZ + tb); uint4 zB = *(uint4*)(tZ + tb + 4);
            s2[0]=sA.x; s2[1]=sA.y; s2[2]=sA.z; s2[3]=sA.w;
            s2[4]=sB.x; s2[5]=sB.y; s2[6]=sB.z; s2[7]=sB.w;
            zp2[0]=zA.x; zp2[1]=zA.y; zp2[2]=zA.z; zp2[3]=zA.w;
            zp2[4]=zB.x; zp2[5]=zB.y; zp2[6]=zB.z; zp2[7]=zB.w;
            if (kt >= 4 && tid < 256) {
                const int gS = gC + 1;
                if (gS < NG) {
                    tS[(gS & 1) * 256 + tid] = h2u(__half2half2(__float2half_rn(sf_next)));
                    tZ[(gS & 1) * 256 + tid] =
                        0x64006400u | (uint32_t)zi_next | ((uint32_t)zi_next << 16);
                }
            }
        }

        // ---- dequant B(kt): 8 half2 (k,k+1 pairs) -> 2 STS.128 (XOR-swizzled) ----
        {
            const uint32_t w0 = (uint32_t)breg0, w1 = (uint32_t)breg1;
            uint32_t q[8];
#pragma unroll
            for (int j = 0; j < 8; j++) {
                uint32_t v = ((w0 >> (4 * j)) & 0xFu) | (((w1 >> (4 * j)) & 0xFu) << 16)
                             | 0x64006400u;
                q[j] = h2u(__hmul2(__hsub2(u2h(v), u2h(zp2[j])), u2h(s2[j])));
            }
            uint32_t* dst = bDst + (kt & 1) * B_STG_U32;
            // element j lives at slot (j ^ wsw): q[0..3] -> +wsw, q[4..7] -> +(wsw^4)
            *(uint4*)(dst + wsw)       = make_uint4(q[0], q[1], q[2], q[3]);
            *(uint4*)(dst + (wsw ^ 4)) = make_uint4(q[4], q[5], q[6], q[7]);
        }

        __syncthreads();

        // ---- compute: 2 ks-steps of m16n8k16 ----
        const uint32_t* Ast = As + (kt & 3) * A_STG_U32;
        const uint32_t* Bst = Bs + (kt & 1) * B_STG_U32;
#pragma unroll
        for (int ks = 0; ks < 2; ks++) {
            uint32_t aF[2][4];
#pragma unroll
            for (int mt = 0; mt < 2; mt++) {
                uint4 v = *(const uint4*)(Ast + ((((wid & 3) * 2 + mt) * 2 + ks) * 128)
                                          + lane * 4);
                aF[mt][0] = v.x; aF[mt][1] = v.y; aF[mt][2] = v.z; aF[mt][3] = v.w;
            }
            const int row0 = ks * 8 + t;
#pragma unroll
            for (int nt = 0; nt < 8; nt++) {
                const int b = (wid >> 2) * 8 + nt;          // n-block (0..31)
                const int offn = b * 8 + (g ^ (b & 4));     // XOR swizzle
                uint32_t b0 = Bst[row0 * BROW + offn];
                uint32_t b1 = Bst[(row0 + 4) * BROW + offn];
#pragma unroll
                for (int mt = 0; mt < 2; mt++)
                    mma_f16(acc[mt][nt][0], acc[mt][nt][1],
                            acc[mt][nt][2], acc[mt][nt][3],
                            aF[mt][0], aF[mt][1], aF[mt][2], aF[mt][3], b0, b1);
            }
        }

        breg0 = bn0; breg1 = bn1;
    }

    // ---- epilogue ----
    const int mwarp = (wid & 3) * 32;
#pragma unroll
    for (int nt = 0; nt < 8; nt++) {
        const int col = n0 + nwarp + nt * 8 + 2 * t;
        const float2 bb = *(const float2*)(bias + col);
#pragma unroll
        for (int mt = 0; mt < 2; mt++) {
            const int row0 = m0 + mwarp + mt * 16 + g;
            *(float2*)(out + (size_t)row0 * N + col) =
                make_float2(acc[mt][nt][0] + bb.x, acc[mt][nt][1] + bb.y);
            *(float2*)(out + (size_t)(row0 + 8) * N + col) =
                make_float2(acc[mt][nt][2] + bb.x, acc[mt][nt][3] + bb.y);
        }
    }
}

extern "C" void kernel_launch(void* const* d_in, const int* in_sizes, int n_in,
                              void* d_out, int out_size)
{
    const float* x      = (const float*)d_in[0];
    const int*   qw     = (const int*)d_in[1];
    const int*   zeros  = (const int*)d_in[2];
    const float* scales = (const float*)d_in[3];
    const float* bias   = (const float*)d_in[4];
    float* out = (float*)d_out;

    const int N = in_sizes[4];                                   // 11008
    const int K = (int)(((long long)in_sizes[1] * 8) / N);       // 4096
    const int M = in_sizes[0] / K;                               // 4096

    const int slabs = (M / 16) * (K / 16);
    xprep_kernel<<<slabs / 4, 128>>>(x, M, K);

    cudaFuncSetAttribute(wq4_mma_kernel,
                         cudaFuncAttributeMaxDynamicSharedMemorySize, SMEM_BYTES);
    dim3 grid(N / BN, M / BM);
    wq4_mma_kernel<<<grid, THREADS, SMEM_BYTES>>>(qw, zeros, scales, bias, out, M, K, N);
}

// round 9
// speedup vs baseline: 5.9995x; 1.1586x over previous
#include <cuda_runtime.h>
#include <cuda_fp16.h>
#include <cstdint>

// W4 group-quant GEMM via mma.sync.m16n8k16.f16 (fp32 accum), base sm_103 PTX.
// out[M,N] = x[M,K] @ dequant(qweight)[K,N] + bias
// R9: 2 CTAs/SM. 256 thr / 8 warps (4M x 2N), BM=128, BN=128, BK=32.
// Per-warp tile (32x64) and inner loop identical to R8; independent CTA
// barriers let one CTA's HMMA cover the other's dequant/barrier phase.
// prep: x fp32 -> fp16 MMA-fragment order scratch (16m x 16k slabs).

#define THREADS 256
#define BM 128
#define BN 128
#define BK 32
#define BROW 136                     // B smem row stride (u32) per k-pair row
#define A_STG_U32 2048               // 8KB per A stage (16 slabs x 128 u32)
#define B_STG_U32 (16 * BROW)        // 2176 u32
#define TAB_OFF (4 * A_STG_U32 + 2 * B_STG_U32)   // 12544
#define SMEM_U32 (TAB_OFF + 512)
#define SMEM_BYTES (SMEM_U32 * 4)    // 52224

#define MAX_MK (4096 * 4096)
__device__ uint32_t g_xa[MAX_MK / 2];   // x as fp16 fragments (32MB)

#define CP_ASYNC16(dst, src) \
    asm volatile("cp.async.ca.shared.global [%0], [%1], 16;" :: "r"(dst), "l"(src))
#define CP_COMMIT() asm volatile("cp.async.commit_group;" ::: "memory")
#define CP_WAIT(N)  asm volatile("cp.async.wait_group %0;" :: "n"(N) : "memory")

__device__ __forceinline__ uint32_t h2u(__half2 h) { return *reinterpret_cast<uint32_t*>(&h); }
__device__ __forceinline__ __half2 u2h(uint32_t u) { return *reinterpret_cast<__half2*>(&u); }

__device__ __forceinline__ void mma_f16(float& c0, float& c1, float& c2, float& c3,
                                        uint32_t a0, uint32_t a1, uint32_t a2, uint32_t a3,
                                        uint32_t b0, uint32_t b1) {
    asm volatile(
        "mma.sync.aligned.m16n8k16.row.col.f32.f16.f16.f32 "
        "{%0,%1,%2,%3}, {%4,%5,%6,%7}, {%8,%9}, {%0,%1,%2,%3};"
        : "+f"(c0), "+f"(c1), "+f"(c2), "+f"(c3)
        : "r"(a0), "r"(a1), "r"(a2), "r"(a3), "r"(b0), "r"(b1));
}

// ---- prep: warp per 16m x 16k slab. lane(g,t): a0=(g,2t..2t+1), a1=(g+8,..),
// a2=(g,2t+8..), a3=(g+8,2t+8..). fp32 -> fp16(rn).
__global__ __launch_bounds__(128)
void xprep_kernel(const float* __restrict__ x, int M, int K)
{
    const int KS = K >> 4;
    const int slab = blockIdx.x * 4 + (threadIdx.x >> 5);
    const int lane = threadIdx.x & 31;
    const int mB = slab / KS;
    const int kB = slab - mB * KS;
    const int g = lane >> 2, t = lane & 3;
    const float* src = x + (size_t)(mB * 16 + g) * K + kB * 16 + 2 * t;
    float2 p00 = *(const float2*)(src);
    float2 p10 = *(const float2*)(src + (size_t)8 * K);
    float2 p01 = *(const float2*)(src + 8);
    float2 p11 = *(const float2*)(src + (size_t)8 * K + 8);
    uint4 v;
    v.x = h2u(__float22half2_rn(p00));
    v.y = h2u(__float22half2_rn(p10));
    v.z = h2u(__float22half2_rn(p01));
    v.w = h2u(__float22half2_rn(p11));
    *(uint4*)(g_xa + (size_t)slab * 128 + lane * 4) = v;
}

__global__ __launch_bounds__(THREADS, 2)
void wq4_mma_kernel(const int*   __restrict__ qw,
                    const int*   __restrict__ zeros,
                    const float* __restrict__ scales,
                    const float* __restrict__ bias,
                    float* __restrict__ out,
                    int M, int K, int N)
{
    extern __shared__ uint32_t sm[];
    uint32_t* As = sm;                         // 4 stages x 2048 u32
    uint32_t* Bs = sm + 4 * A_STG_U32;         // 2 stages x 2176 u32
    uint32_t* tS = sm + TAB_OFF;               // [2][128] half2-dup scales
    uint32_t* tZ = tS + 256;                   // [2][128] half2 zero-points

    const int tid  = threadIdx.x;
    const int wid  = tid >> 5;
    const int lane = tid & 31;
    const int g    = lane >> 2;
    const int t    = lane & 3;

    const int n0 = blockIdx.x * BN;
    const int m0 = blockIdx.y * BM;
    const int nq = N >> 3;
    const int NT = K / BK;                     // 128
    const int NG = K >> 7;                     // 32 groups

    // ---- A cp.async: 2 x 16B per thread per stage ----
    const int KSLAB = K >> 4;
    const int ci0 = tid, ci1 = tid + 256;
    const uint32_t* aSrc0 = g_xa + ((size_t)((m0 >> 4) + ((ci0 >> 5) >> 1)) * KSLAB
                            + ((ci0 >> 5) & 1)) * 128 + (ci0 & 31) * 4;
    const uint32_t* aSrc1 = g_xa + ((size_t)((m0 >> 4) + ((ci1 >> 5) >> 1)) * KSLAB
                            + ((ci1 >> 5) & 1)) * 128 + (ci1 & 31) * 4;
    const uint32_t aDst0 = (uint32_t)__cvta_generic_to_shared(As) + (uint32_t)ci0 * 16;
    const uint32_t aDst1 = (uint32_t)__cvta_generic_to_shared(As) + (uint32_t)ci1 * 16;

    // ---- B: kp = tid>>4 (16 k-pair rows), w = tid&15 (8 n each) ----
    const int kp = tid >> 4, w = tid & 15;
    const int* qP = qw + (size_t)(2 * kp) * nq + (n0 >> 3) + w;
    const int wsw = w & 4;                     // XOR swizzle selector
    uint32_t* bDst = Bs + kp * BROW + w * 8;

    float acc[2][8][4];
#pragma unroll
    for (int i = 0; i < 2; i++)
#pragma unroll
        for (int j = 0; j < 8; j++)
#pragma unroll
            for (int r = 0; r < 4; r++) acc[i][j][r] = 0.f;

    // ---- prologue: tables for groups 0,1 ----
    if (tid < 128) {
#pragma unroll
        for (int gg = 0; gg < 2; gg++) {
            float s = scales[(size_t)gg * N + n0 + tid];
            int   z = zeros[(size_t)gg * N + n0 + tid];
            tS[gg * 128 + tid] = h2u(__half2half2(__float2half_rn(s)));
            tZ[gg * 128 + tid] = 0x64006400u | (uint32_t)z | ((uint32_t)z << 16);
        }
    }

    // issue A tiles 0,1
    CP_ASYNC16(aDst0, aSrc0);
    CP_ASYNC16(aDst1, aSrc1);
    CP_COMMIT();
    CP_ASYNC16(aDst0 + A_STG_U32 * 4, aSrc0 + 256);
    CP_ASYNC16(aDst1 + A_STG_U32 * 4, aSrc1 + 256);
    CP_COMMIT();

    __syncthreads();   // tables visible

    int breg0 = qP[0], breg1 = qP[nq];
    int bn0 = 0, bn1 = 0;
    float sf_next = 0.f; int zi_next = 0;
    uint32_t s2[8], zp2[8];

    for (int kt = 0; kt < NT; kt++) {
        // ---- prefetch A(kt+2), B(kt+1), table LDG ----
        if (kt < NT - 2) {
            const uint32_t so = (uint32_t)((kt + 2) & 3) * (A_STG_U32 * 4);
            const size_t go = (size_t)(kt + 2) * 256;
            CP_ASYNC16(aDst0 + so, aSrc0 + go);
            CP_ASYNC16(aDst1 + so, aSrc1 + go);
            CP_COMMIT();
        }
        if (kt < NT - 1) {
            const int* qn = qP + (size_t)(kt + 1) * 32 * nq;
            bn0 = qn[0]; bn1 = qn[nq];
        }
        if ((kt & 3) == 2 && tid < 128) {
            const int gL = (kt >> 2) + 2;
            if (gL < NG) {
                sf_next = scales[(size_t)gL * N + n0 + tid];
                zi_next = zeros[(size_t)gL * N + n0 + tid];
            }
        }

        if (kt < NT - 2)       { CP_WAIT(2); }
        else if (kt == NT - 2) { CP_WAIT(1); }
        else                   { CP_WAIT(0); }

        if ((kt & 3) == 0) {
            const int gC = kt >> 2;
            const int tb = (gC & 1) * 128 + w * 8;
            uint4 sA = *(uint4*)(tS + tb); uint4 sB = *(uint4*)(tS + tb + 4);
            uint4 zA = *(uint4*)(tZ + tb); uint4 zB = *(uint4*)(tZ + tb + 4);
            s2[0]=sA.x; s2[1]=sA.y; s2[2]=sA.z; s2[3]=sA.w;
            s2[4]=sB.x; s2[5]=sB.y; s2[6]=sB.z; s2[7]=sB.w;
            zp2[0]=zA.x; zp2[1]=zA.y; zp2[2]=zA.z; zp2[3]=zA.w;
            zp2[4]=zB.x; zp2[5]=zB.y; zp2[6]=zB.z; zp2[7]=zB.w;
            if (kt >= 4 && tid < 128) {
                const int gS = gC + 1;
                if (gS < NG) {
                    tS[(gS & 1) * 128 + tid] = h2u(__half2half2(__float2half_rn(sf_next)));
                    tZ[(gS & 1) * 128 + tid] =
                        0x64006400u | (uint32_t)zi_next | ((uint32_t)zi_next << 16);
                }
            }
        }

        // ---- dequant B(kt): 8 half2 (k,k+1 pairs) -> 2 STS.128 (XOR-swizzled) ----
        {
            const uint32_t w0 = (uint32_t)breg0, w1 = (uint32_t)breg1;
            uint32_t q[8];
#pragma unroll
            for (int j = 0; j < 8; j++) {
                uint32_t v = ((w0 >> (4 * j)) & 0xFu) | (((w1 >> (4 * j)) & 0xFu) << 16)
                             | 0x64006400u;
                q[j] = h2u(__hmul2(__hsub2(u2h(v), u2h(zp2[j])), u2h(s2[j])));
            }
            uint32_t* dst = bDst + (kt & 1) * B_STG_U32;
            *(uint4*)(dst + wsw)       = make_uint4(q[0], q[1], q[2], q[3]);
            *(uint4*)(dst + (wsw ^ 4)) = make_uint4(q[4], q[5], q[6], q[7]);
        }

        __syncthreads();

        // ---- compute: 2 ks-steps of m16n8k16, warp tile 32m x 64n ----
        const uint32_t* Ast = As + (kt & 3) * A_STG_U32;
        const uint32_t* Bst = Bs + (kt & 1) * B_STG_U32;
#pragma unroll
        for (int ks = 0; ks < 2; ks++) {
            uint32_t aF[2][4];
#pragma unroll
            for (int mt = 0; mt < 2; mt++) {
                uint4 v = *(const uint4*)(Ast + ((((wid & 3) * 2 + mt) * 2 + ks) * 128)
                                          + lane * 4);
                aF[mt][0] = v.x; aF[mt][1] = v.y; aF[mt][2] = v.z; aF[mt][3] = v.w;
            }
            const int row0 = ks * 8 + t;
#pragma unroll
            for (int nt = 0; nt < 8; nt++) {
                const int b = (wid >> 2) * 8 + nt;          // n-block (0..15)
                const int offn = b * 8 + (g ^ (b & 4));     // XOR swizzle
                uint32_t b0 = Bst[row0 * BROW + offn];
                uint32_t b1 = Bst[(row0 + 4) * BROW + offn];
#pragma unroll
                for (int mt = 0; mt < 2; mt++)
                    mma_f16(acc[mt][nt][0], acc[mt][nt][1],
                            acc[mt][nt][2], acc[mt][nt][3],
                            aF[mt][0], aF[mt][1], aF[mt][2], aF[mt][3], b0, b1);
            }
        }

        breg0 = bn0; breg1 = bn1;
    }

    // ---- epilogue ----
    const int mwarp = (wid & 3) * 32;
    const int nwarp = (wid >> 2) * 64;
#pragma unroll
    for (int nt = 0; nt < 8; nt++) {
        const int col = n0 + nwarp + nt * 8 + 2 * t;
        const float2 bb = *(const float2*)(bias + col);
#pragma unroll
        for (int mt = 0; mt < 2; mt++) {
            const int row0 = m0 + mwarp + mt * 16 + g;
            *(float2*)(out + (size_t)row0 * N + col) =
                make_float2(acc[mt][nt][0] + bb.x, acc[mt][nt][1] + bb.y);
            *(float2*)(out + (size_t)(row0 + 8) * N + col) =
                make_float2(acc[mt][nt][2] + bb.x, acc[mt][nt][3] + bb.y);
        }
    }
}

extern "C" void kernel_launch(void* const* d_in, const int* in_sizes, int n_in,
                              void* d_out, int out_size)
{
    const float* x      = (const float*)d_in[0];
    const int*   qw     = (const int*)d_in[1];
    const int*   zeros  = (const int*)d_in[2];
    const float* scales = (const float*)d_in[3];
    const float* bias   = (const float*)d_in[4];
    float* out = (float*)d_out;

    const int N = in_sizes[4];                                   // 11008
    const int K = (int)(((long long)in_sizes[1] * 8) / N);       // 4096
    const int M = in_sizes[0] / K;                               // 4096

    const int slabs = (M / 16) * (K / 16);
    xprep_kernel<<<slabs / 4, 128>>>(x, M, K);

    cudaFuncSetAttribute(wq4_mma_kernel,
                         cudaFuncAttributeMaxDynamicSharedMemorySize, SMEM_BYTES);
    dim3 grid(N / BN, M / BM);
    wq4_mma_kernel<<<grid, THREADS, SMEM_BYTES>>>(qw, zeros, scales, bias, out, M, K, N);
}

// round 10
// speedup vs baseline: 6.6855x; 1.1143x over previous
#include <cuda_runtime.h>
#include <cuda_fp16.h>
#include <cstdint>

// W4 group-quant GEMM via mma.sync.m16n8k16.f16 (fp32 accum), base sm_103 PTX.
// out[M,N] = x[M,K] @ dequant(qweight)[K,N] + bias
// R10 = R9 + (a) B qweight prefetch 2 tiles deep (was 1; LDG latency exposed),
//            (b) PRMT+LOP3 nibble dequant (2 ops/pair vs ~6).
// 2 CTAs/SM: 256 thr / 8 warps (4M x 2N), BM=128, BN=128, BK=32.

#define THREADS 256
#define BM 128
#define BN 128
#define BK 32
#define BROW 136                     // B smem row stride (u32) per k-pair row
#define A_STG_U32 2048               // 8KB per A stage (16 slabs x 128 u32)
#define B_STG_U32 (16 * BROW)        // 2176 u32
#define TAB_OFF (4 * A_STG_U32 + 2 * B_STG_U32)   // 12544
#define SMEM_U32 (TAB_OFF + 512)
#define SMEM_BYTES (SMEM_U32 * 4)    // 52224

#define MAX_MK (4096 * 4096)
__device__ uint32_t g_xa[MAX_MK / 2];   // x as fp16 fragments (32MB)

#define CP_ASYNC16(dst, src) \
    asm volatile("cp.async.ca.shared.global [%0], [%1], 16;" :: "r"(dst), "l"(src))
#define CP_COMMIT() asm volatile("cp.async.commit_group;" ::: "memory")
#define CP_WAIT(N)  asm volatile("cp.async.wait_group %0;" :: "n"(N) : "memory")

__device__ __forceinline__ uint32_t h2u(__half2 h) { return *reinterpret_cast<uint32_t*>(&h); }
__device__ __forceinline__ __half2 u2h(uint32_t u) { return *reinterpret_cast<__half2*>(&u); }

__device__ __forceinline__ void mma_f16(float& c0, float& c1, float& c2, float& c3,
                                        uint32_t a0, uint32_t a1, uint32_t a2, uint32_t a3,
                                        uint32_t b0, uint32_t b1) {
    asm volatile(
        "mma.sync.aligned.m16n8k16.row.col.f32.f16.f16.f32 "
        "{%0,%1,%2,%3}, {%4,%5,%6,%7}, {%8,%9}, {%0,%1,%2,%3};"
        : "+f"(c0), "+f"(c1), "+f"(c2), "+f"(c3)
        : "r"(a0), "r"(a1), "r"(a2), "r"(a3), "r"(b0), "r"(b1));
}

// ---- prep: warp per 16m x 16k slab. lane(g,t): a0=(g,2t..2t+1), a1=(g+8,..),
// a2=(g,2t+8..), a3=(g+8,2t+8..). fp32 -> fp16(rn).
__global__ __launch_bounds__(128)
void xprep_kernel(const float* __restrict__ x, int M, int K)
{
    const int KS = K >> 4;
    const int slab = blockIdx.x * 4 + (threadIdx.x >> 5);
    const int lane = threadIdx.x & 31;
    const int mB = slab / KS;
    const int kB = slab - mB * KS;
    const int g = lane >> 2, t = lane & 3;
    const float* src = x + (size_t)(mB * 16 + g) * K + kB * 16 + 2 * t;
    float2 p00 = *(const float2*)(src);
    float2 p10 = *(const float2*)(src + (size_t)8 * K);
    float2 p01 = *(const float2*)(src + 8);
    float2 p11 = *(const float2*)(src + (size_t)8 * K + 8);
    uint4 v;
    v.x = h2u(__float22half2_rn(p00));
    v.y = h2u(__float22half2_rn(p10));
    v.z = h2u(__float22half2_rn(p01));
    v.w = h2u(__float22half2_rn(p11));
    *(uint4*)(g_xa + (size_t)slab * 128 + lane * 4) = v;
}

__global__ __launch_bounds__(THREADS, 2)
void wq4_mma_kernel(const int*   __restrict__ qw,
                    const int*   __restrict__ zeros,
                    const float* __restrict__ scales,
                    const float* __restrict__ bias,
                    float* __restrict__ out,
                    int M, int K, int N)
{
    extern __shared__ uint32_t sm[];
    uint32_t* As = sm;                         // 4 stages x 2048 u32
    uint32_t* Bs = sm + 4 * A_STG_U32;         // 2 stages x 2176 u32
    uint32_t* tS = sm + TAB_OFF;               // [2][128] half2-dup scales
    uint32_t* tZ = tS + 256;                   // [2][128] half2 zero-points

    const int tid  = threadIdx.x;
    const int wid  = tid >> 5;
    const int lane = tid & 31;
    const int g    = lane >> 2;
    const int t    = lane & 3;

    const int n0 = blockIdx.x * BN;
    const int m0 = blockIdx.y * BM;
    const int nq = N >> 3;
    const int NT = K / BK;                     // 128
    const int NG = K >> 7;                     // 32 groups

    // ---- A cp.async: 2 x 16B per thread per stage ----
    const int KSLAB = K >> 4;
    const int ci0 = tid, ci1 = tid + 256;
    const uint32_t* aSrc0 = g_xa + ((size_t)((m0 >> 4) + ((ci0 >> 5) >> 1)) * KSLAB
                            + ((ci0 >> 5) & 1)) * 128 + (ci0 & 31) * 4;
    const uint32_t* aSrc1 = g_xa + ((size_t)((m0 >> 4) + ((ci1 >> 5) >> 1)) * KSLAB
                            + ((ci1 >> 5) & 1)) * 128 + (ci1 & 31) * 4;
    const uint32_t aDst0 = (uint32_t)__cvta_generic_to_shared(As) + (uint32_t)ci0 * 16;
    const uint32_t aDst1 = (uint32_t)__cvta_generic_to_shared(As) + (uint32_t)ci1 * 16;

    // ---- B: kp = tid>>4 (16 k-pair rows), w = tid&15 (8 n each) ----
    const int kp = tid >> 4, w = tid & 15;
    const int* qP = qw + (size_t)(2 * kp) * nq + (n0 >> 3) + w;
    const int wsw = w & 4;                     // XOR swizzle selector
    uint32_t* bDst = Bs + kp * BROW + w * 8;

    float acc[2][8][4];
#pragma unroll
    for (int i = 0; i < 2; i++)
#pragma unroll
        for (int j = 0; j < 8; j++)
#pragma unroll
            for (int r = 0; r < 4; r++) acc[i][j][r] = 0.f;

    // ---- prologue: tables for groups 0,1 ----
    if (tid < 128) {
#pragma unroll
        for (int gg = 0; gg < 2; gg++) {
            float s = scales[(size_t)gg * N + n0 + tid];
            int   z = zeros[(size_t)gg * N + n0 + tid];
            tS[gg * 128 + tid] = h2u(__half2half2(__float2half_rn(s)));
            tZ[gg * 128 + tid] = 0x64006400u | (uint32_t)z | ((uint32_t)z << 16);
        }
    }

    // issue A tiles 0,1
    CP_ASYNC16(aDst0, aSrc0);
    CP_ASYNC16(aDst1, aSrc1);
    CP_COMMIT();
    CP_ASYNC16(aDst0 + A_STG_U32 * 4, aSrc0 + 256);
    CP_ASYNC16(aDst1 + A_STG_U32 * 4, aSrc1 + 256);
    CP_COMMIT();

    __syncthreads();   // tables visible

    // ---- B qweight registers: 2-deep prefetch ----
    int b0a = qP[0],                     b0b = qP[nq];
    int b1a = qP[(size_t)32 * nq],       b1b = qP[(size_t)32 * nq + nq];
    int b2a = 0, b2b = 0;
    float sf_next = 0.f; int zi_next = 0;
    uint32_t s2[8], zp2[8];

    for (int kt = 0; kt < NT; kt++) {
        // ---- prefetch A(kt+2), B(kt+2), table LDG ----
        if (kt < NT - 2) {
            const uint32_t so = (uint32_t)((kt + 2) & 3) * (A_STG_U32 * 4);
            const size_t go = (size_t)(kt + 2) * 256;
            CP_ASYNC16(aDst0 + so, aSrc0 + go);
            CP_ASYNC16(aDst1 + so, aSrc1 + go);
            CP_COMMIT();
            const int* qn = qP + (size_t)(kt + 2) * 32 * nq;
            b2a = qn[0]; b2b = qn[nq];
        }
        if ((kt & 3) == 2 && tid < 128) {
            const int gL = (kt >> 2) + 2;
            if (gL < NG) {
                sf_next = scales[(size_t)gL * N + n0 + tid];
                zi_next = zeros[(size_t)gL * N + n0 + tid];
            }
        }

        if (kt < NT - 2)       { CP_WAIT(2); }
        else if (kt == NT - 2) { CP_WAIT(1); }
        else                   { CP_WAIT(0); }

        if ((kt & 3) == 0) {
            const int gC = kt >> 2;
            const int tb = (gC & 1) * 128 + w * 8;
            uint4 sA = *(uint4*)(tS + tb); uint4 sB = *(uint4*)(tS + tb + 4);
            uint4 zA = *(uint4*)(tZ + tb); uint4 zB = *(uint4*)(tZ + tb + 4);
            s2[0]=sA.x; s2[1]=sA.y; s2[2]=sA.z; s2[3]=sA.w;
            s2[4]=sB.x; s2[5]=sB.y; s2[6]=sB.z; s2[7]=sB.w;
            zp2[0]=zA.x; zp2[1]=zA.y; zp2[2]=zA.z; zp2[3]=zA.w;
            zp2[4]=zB.x; zp2[5]=zB.y; zp2[6]=zB.z; zp2[7]=zB.w;
            if (kt >= 4 && tid < 128) {
                const int gS = gC + 1;
                if (gS < NG) {
                    tS[(gS & 1) * 128 + tid] = h2u(__half2half2(__float2half_rn(sf_next)));
                    tZ[(gS & 1) * 128 + tid] =
                        0x64006400u | (uint32_t)zi_next | ((uint32_t)zi_next << 16);
                }
            }
        }

        // ---- dequant B(kt): PRMT interleave + LOP3 extract, 8 half2 ----
        {
            const uint32_t w0 = (uint32_t)b0a, w1 = (uint32_t)b0b;
            // c1: n1n0 | n3n2 | m1m0 | m3m2  (n = w0 nibbles, m = w1 nibbles)
            const uint32_t c1 = __byte_perm(w0, w1, 0x5410);
            const uint32_t c2 = __byte_perm(w0, w1, 0x7632);
            uint32_t q[8];
            q[0] = (c1         & 0x000F000Fu) | 0x64006400u;
            q[1] = ((c1 >> 4)  & 0x000F000Fu) | 0x64006400u;
            q[2] = ((c1 >> 8)  & 0x000F000Fu) | 0x64006400u;
            q[3] = ((c1 >> 12) & 0x000F000Fu) | 0x64006400u;
            q[4] = (c2         & 0x000F000Fu) | 0x64006400u;
            q[5] = ((c2 >> 4)  & 0x000F000Fu) | 0x64006400u;
            q[6] = ((c2 >> 8)  & 0x000F000Fu) | 0x64006400u;
            q[7] = ((c2 >> 12) & 0x000F000Fu) | 0x64006400u;
#pragma unroll
            for (int j = 0; j < 8; j++)
                q[j] = h2u(__hmul2(__hsub2(u2h(q[j]), u2h(zp2[j])), u2h(s2[j])));
            uint32_t* dst = bDst + (kt & 1) * B_STG_U32;
            *(uint4*)(dst + wsw)       = make_uint4(q[0], q[1], q[2], q[3]);
            *(uint4*)(dst + (wsw ^ 4)) = make_uint4(q[4], q[5], q[6], q[7]);
        }

        __syncthreads();

        // ---- compute: 2 ks-steps of m16n8k16, warp tile 32m x 64n ----
        const uint32_t* Ast = As + (kt & 3) * A_STG_U32;
        const uint32_t* Bst = Bs + (kt & 1) * B_STG_U32;
#pragma unroll
        for (int ks = 0; ks < 2; ks++) {
            uint32_t aF[2][4];
#pragma unroll
            for (int mt = 0; mt < 2; mt++) {
                uint4 v = *(const uint4*)(Ast + ((((wid & 3) * 2 + mt) * 2 + ks) * 128)
                                          + lane * 4);
                aF[mt][0] = v.x; aF[mt][1] = v.y; aF[mt][2] = v.z; aF[mt][3] = v.w;
            }
            const int row0 = ks * 8 + t;
#pragma unroll
            for (int nt = 0; nt < 8; nt++) {
                const int b = (wid >> 2) * 8 + nt;          // n-block (0..15)
                const int offn = b * 8 + (g ^ (b & 4));     // XOR swizzle
                uint32_t b0 = Bst[row0 * BROW + offn];
                uint32_t b1 = Bst[(row0 + 4) * BROW + offn];
#pragma unroll
                for (int mt = 0; mt < 2; mt++)
                    mma_f16(acc[mt][nt][0], acc[mt][nt][1],
                            acc[mt][nt][2], acc[mt][nt][3],
                            aF[mt][0], aF[mt][1], aF[mt][2], aF[mt][3], b0, b1);
            }
        }

        b0a = b1a; b0b = b1b;
        b1a = b2a; b1b = b2b;
    }

    // ---- epilogue ----
    const int mwarp = (wid & 3) * 32;
    const int nwarp = (wid >> 2) * 64;
#pragma unroll
    for (int nt = 0; nt < 8; nt++) {
        const int col = n0 + nwarp + nt * 8 + 2 * t;
        const float2 bb = *(const float2*)(bias + col);
#pragma unroll
        for (int mt = 0; mt < 2; mt++) {
            const int row0 = m0 + mwarp + mt * 16 + g;
            *(float2*)(out + (size_t)row0 * N + col) =
                make_float2(acc[mt][nt][0] + bb.x, acc[mt][nt][1] + bb.y);
            *(float2*)(out + (size_t)(row0 + 8) * N + col) =
                make_float2(acc[mt][nt][2] + bb.x, acc[mt][nt][3] + bb.y);
        }
    }
}

extern "C" void kernel_launch(void* const* d_in, const int* in_sizes, int n_in,
                              void* d_out, int out_size)
{
    const float* x      = (const float*)d_in[0];
    const int*   qw     = (const int*)d_in[1];
    const int*   zeros  = (const int*)d_in[2];
    const float* scales = (const float*)d_in[3];
    const float* bias   = (const float*)d_in[4];
    float* out = (float*)d_out;

    const int N = in_sizes[4];                                   // 11008
    const int K = (int)(((long long)in_sizes[1] * 8) / N);       // 4096
    const int M = in_sizes[0] / K;                               // 4096

    const int slabs = (M / 16) * (K / 16);
    xprep_kernel<<<slabs / 4, 128>>>(x, M, K);

    cudaFuncSetAttribute(wq4_mma_kernel,
                         cudaFuncAttributeMaxDynamicSharedMemorySize, SMEM_BYTES);
    dim3 grid(N / BN, M / BM);
    wq4_mma_kernel<<<grid, THREADS, SMEM_BYTES>>>(qw, zeros, scales, bias, out, M, K, N);
}

// round 11
// speedup vs baseline: 6.6861x; 1.0001x over previous
#include <cuda_runtime.h>
#include <cuda_fp16.h>
#include <cstdint>

// W4 group-quant GEMM via mma.sync.m16n8k16.f16 (fp32 accum), base sm_103 PTX.
// out[M,N] = x[M,K] @ dequant(qweight)[K,N] + bias
// R10 = R9 + (a) B qweight prefetch 2 tiles deep (was 1; LDG latency exposed),
//            (b) PRMT+LOP3 nibble dequant (2 ops/pair vs ~6).
// 2 CTAs/SM: 256 thr / 8 warps (4M x 2N), BM=128, BN=128, BK=32.

#define THREADS 256
#define BM 128
#define BN 128
#define BK 32
#define BROW 136                     // B smem row stride (u32) per k-pair row
#define A_STG_U32 2048               // 8KB per A stage (16 slabs x 128 u32)
#define B_STG_U32 (16 * BROW)        // 2176 u32
#define TAB_OFF (4 * A_STG_U32 + 2 * B_STG_U32)   // 12544
#define SMEM_U32 (TAB_OFF + 512)
#define SMEM_BYTES (SMEM_U32 * 4)    // 52224

#define MAX_MK (4096 * 4096)
__device__ uint32_t g_xa[MAX_MK / 2];   // x as fp16 fragments (32MB)

#define CP_ASYNC16(dst, src) \
    asm volatile("cp.async.ca.shared.global [%0], [%1], 16;" :: "r"(dst), "l"(src))
#define CP_COMMIT() asm volatile("cp.async.commit_group;" ::: "memory")
#define CP_WAIT(N)  asm volatile("cp.async.wait_group %0;" :: "n"(N) : "memory")

__device__ __forceinline__ uint32_t h2u(__half2 h) { return *reinterpret_cast<uint32_t*>(&h); }
__device__ __forceinline__ __half2 u2h(uint32_t u) { return *reinterpret_cast<__half2*>(&u); }

__device__ __forceinline__ void mma_f16(float& c0, float& c1, float& c2, float& c3,
                                        uint32_t a0, uint32_t a1, uint32_t a2, uint32_t a3,
                                        uint32_t b0, uint32_t b1) {
    asm volatile(
        "mma.sync.aligned.m16n8k16.row.col.f32.f16.f16.f32 "
        "{%0,%1,%2,%3}, {%4,%5,%6,%7}, {%8,%9}, {%0,%1,%2,%3};"
        : "+f"(c0), "+f"(c1), "+f"(c2), "+f"(c3)
        : "r"(a0), "r"(a1), "r"(a2), "r"(a3), "r"(b0), "r"(b1));
}

// ---- prep: warp per 16m x 16k slab. lane(g,t): a0=(g,2t..2t+1), a1=(g+8,..),
// a2=(g,2t+8..), a3=(g+8,2t+8..). fp32 -> fp16(rn).
__global__ __launch_bounds__(128)
void xprep_kernel(const float* __restrict__ x, int M, int K)
{
    const int KS = K >> 4;
    const int slab = blockIdx.x * 4 + (threadIdx.x >> 5);
    const int lane = threadIdx.x & 31;
    const int mB = slab / KS;
    const int kB = slab - mB * KS;
    const int g = lane >> 2, t = lane & 3;
    const float* src = x + (size_t)(mB * 16 + g) * K + kB * 16 + 2 * t;
    float2 p00 = *(const float2*)(src);
    float2 p10 = *(const float2*)(src + (size_t)8 * K);
    float2 p01 = *(const float2*)(src + 8);
    float2 p11 = *(const float2*)(src + (size_t)8 * K + 8);
    uint4 v;
    v.x = h2u(__float22half2_rn(p00));
    v.y = h2u(__float22half2_rn(p10));
    v.z = h2u(__float22half2_rn(p01));
    v.w = h2u(__float22half2_rn(p11));
    *(uint4*)(g_xa + (size_t)slab * 128 + lane * 4) = v;
}

__global__ __launch_bounds__(THREADS, 2)
void wq4_mma_kernel(const int*   __restrict__ qw,
                    const int*   __restrict__ zeros,
                    const float* __restrict__ scales,
                    const float* __restrict__ bias,
                    float* __restrict__ out,
                    int M, int K, int N)
{
    extern __shared__ uint32_t sm[];
    uint32_t* As = sm;                         // 4 stages x 2048 u32
    uint32_t* Bs = sm + 4 * A_STG_U32;         // 2 stages x 2176 u32
    uint32_t* tS = sm + TAB_OFF;               // [2][128] half2-dup scales
    uint32_t* tZ = tS + 256;                   // [2][128] half2 zero-points

    const int tid  = threadIdx.x;
    const int wid  = tid >> 5;
    const int lane = tid & 31;
    const int g    = lane >> 2;
    const int t    = lane & 3;

    const int n0 = blockIdx.x * BN;
    const int m0 = blockIdx.y * BM;
    const int nq = N >> 3;
    const int NT = K / BK;                     // 128
    const int NG = K >> 7;                     // 32 groups

    // ---- A cp.async: 2 x 16B per thread per stage ----
    const int KSLAB = K >> 4;
    const int ci0 = tid, ci1 = tid + 256;
    const uint32_t* aSrc0 = g_xa + ((size_t)((m0 >> 4) + ((ci0 >> 5) >> 1)) * KSLAB
                            + ((ci0 >> 5) & 1)) * 128 + (ci0 & 31) * 4;
    const uint32_t* aSrc1 = g_xa + ((size_t)((m0 >> 4) + ((ci1 >> 5) >> 1)) * KSLAB
                            + ((ci1 >> 5) & 1)) * 128 + (ci1 & 31) * 4;
    const uint32_t aDst0 = (uint32_t)__cvta_generic_to_shared(As) + (uint32_t)ci0 * 16;
    const uint32_t aDst1 = (uint32_t)__cvta_generic_to_shared(As) + (uint32_t)ci1 * 16;

    // ---- B: kp = tid>>4 (16 k-pair rows), w = tid&15 (8 n each) ----
    const int kp = tid >> 4, w = tid & 15;
    const int* qP = qw + (size_t)(2 * kp) * nq + (n0 >> 3) + w;
    const int wsw = w & 4;                     // XOR swizzle selector
    uint32_t* bDst = Bs + kp * BROW + w * 8;

    float acc[2][8][4];
#pragma unroll
    for (int i = 0; i < 2; i++)
#pragma unroll
        for (int j = 0; j < 8; j++)
#pragma unroll
            for (int r = 0; r < 4; r++) acc[i][j][r] = 0.f;

    // ---- prologue: tables for groups 0,1 ----
    if (tid < 128) {
#pragma unroll
        for (int gg = 0; gg < 2; gg++) {
            float s = scales[(size_t)gg * N + n0 + tid];
            int   z = zeros[(size_t)gg * N + n0 + tid];
            tS[gg * 128 + tid] = h2u(__half2half2(__float2half_rn(s)));
            tZ[gg * 128 + tid] = 0x64006400u | (uint32_t)z | ((uint32_t)z << 16);
        }
    }

    // issue A tiles 0,1
    CP_ASYNC16(aDst0, aSrc0);
    CP_ASYNC16(aDst1, aSrc1);
    CP_COMMIT();
    CP_ASYNC16(aDst0 + A_STG_U32 * 4, aSrc0 + 256);
    CP_ASYNC16(aDst1 + A_STG_U32 * 4, aSrc1 + 256);
    CP_COMMIT();

    __syncthreads();   // tables visible

    // ---- B qweight registers: 2-deep prefetch ----
    int b0a = qP[0],                     b0b = qP[nq];
    int b1a = qP[(size_t)32 * nq],       b1b = qP[(size_t)32 * nq + nq];
    int b2a = 0, b2b = 0;
    float sf_next = 0.f; int zi_next = 0;
    uint32_t s2[8], zp2[8];

    for (int kt = 0; kt < NT; kt++) {
        // ---- prefetch A(kt+2), B(kt+2), table LDG ----
        if (kt < NT - 2) {
            const uint32_t so = (uint32_t)((kt + 2) & 3) * (A_STG_U32 * 4);
            const size_t go = (size_t)(kt + 2) * 256;
            CP_ASYNC16(aDst0 + so, aSrc0 + go);
            CP_ASYNC16(aDst1 + so, aSrc1 + go);
            CP_COMMIT();
            const int* qn = qP + (size_t)(kt + 2) * 32 * nq;
            b2a = qn[0]; b2b = qn[nq];
        }
        if ((kt & 3) == 2 && tid < 128) {
            const int gL = (kt >> 2) + 2;
            if (gL < NG) {
                sf_next = scales[(size_t)gL * N + n0 + tid];
                zi_next = zeros[(size_t)gL * N + n0 + tid];
            }
        }

        if (kt < NT - 2)       { CP_WAIT(2); }
        else if (kt == NT - 2) { CP_WAIT(1); }
        else                   { CP_WAIT(0); }

        if ((kt & 3) == 0) {
            const int gC = kt >> 2;
            const int tb = (gC & 1) * 128 + w * 8;
            uint4 sA = *(uint4*)(tS + tb); uint4 sB = *(uint4*)(tS + tb + 4);
            uint4 zA = *(uint4*)(tZ + tb); uint4 zB = *(uint4*)(tZ + tb + 4);
            s2[0]=sA.x; s2[1]=sA.y; s2[2]=sA.z; s2[3]=sA.w;
            s2[4]=sB.x; s2[5]=sB.y; s2[6]=sB.z; s2[7]=sB.w;
            zp2[0]=zA.x; zp2[1]=zA.y; zp2[2]=zA.z; zp2[3]=zA.w;
            zp2[4]=zB.x; zp2[5]=zB.y; zp2[6]=zB.z; zp2[7]=zB.w;
            if (kt >= 4 && tid < 128) {
                const int gS = gC + 1;
                if (gS < NG) {
                    tS[(gS & 1) * 128 + tid] = h2u(__half2half2(__float2half_rn(sf_next)));
                    tZ[(gS & 1) * 128 + tid] =
                        0x64006400u | (uint32_t)zi_next | ((uint32_t)zi_next << 16);
                }
            }
        }

        // ---- dequant B(kt): PRMT interleave + LOP3 extract, 8 half2 ----
        {
            const uint32_t w0 = (uint32_t)b0a, w1 = (uint32_t)b0b;
            // c1: n1n0 | n3n2 | m1m0 | m3m2  (n = w0 nibbles, m = w1 nibbles)
            const uint32_t c1 = __byte_perm(w0, w1, 0x5410);
            const uint32_t c2 = __byte_perm(w0, w1, 0x7632);
            uint32_t q[8];
            q[0] = (c1         & 0x000F000Fu) | 0x64006400u;
            q[1] = ((c1 >> 4)  & 0x000F000Fu) | 0x64006400u;
            q[2] = ((c1 >> 8)  & 0x000F000Fu) | 0x64006400u;
            q[3] = ((c1 >> 12) & 0x000F000Fu) | 0x64006400u;
            q[4] = (c2         & 0x000F000Fu) | 0x64006400u;
            q[5] = ((c2 >> 4)  & 0x000F000Fu) | 0x64006400u;
            q[6] = ((c2 >> 8)  & 0x000F000Fu) | 0x64006400u;
            q[7] = ((c2 >> 12) & 0x000F000Fu) | 0x64006400u;
#pragma unroll
            for (int j = 0; j < 8; j++)
                q[j] = h2u(__hmul2(__hsub2(u2h(q[j]), u2h(zp2[j])), u2h(s2[j])));
            uint32_t* dst = bDst + (kt & 1) * B_STG_U32;
            *(uint4*)(dst + wsw)       = make_uint4(q[0], q[1], q[2], q[3]);
            *(uint4*)(dst + (wsw ^ 4)) = make_uint4(q[4], q[5], q[6], q[7]);
        }

        __syncthreads();

        // ---- compute: 2 ks-steps of m16n8k16, warp tile 32m x 64n ----
        const uint32_t* Ast = As + (kt & 3) * A_STG_U32;
        const uint32_t* Bst = Bs + (kt & 1) * B_STG_U32;
#pragma unroll
        for (int ks = 0; ks < 2; ks++) {
            uint32_t aF[2][4];
#pragma unroll
            for (int mt = 0; mt < 2; mt++) {
                uint4 v = *(const uint4*)(Ast + ((((wid & 3) * 2 + mt) * 2 + ks) * 128)
                                          + lane * 4);
                aF[mt][0] = v.x; aF[mt][1] = v.y; aF[mt][2] = v.z; aF[mt][3] = v.w;
            }
            const int row0 = ks * 8 + t;
#pragma unroll
            for (int nt = 0; nt < 8; nt++) {
                const int b = (wid >> 2) * 8 + nt;          // n-block (0..15)
                const int offn = b * 8 + (g ^ (b & 4));     // XOR swizzle
                uint32_t b0 = Bst[row0 * BROW + offn];
                uint32_t b1 = Bst[(row0 + 4) * BROW + offn];
#pragma unroll
                for (int mt = 0; mt < 2; mt++)
                    mma_f16(acc[mt][nt][0], acc[mt][nt][1],
                            acc[mt][nt][2], acc[mt][nt][3],
                            aF[mt][0], aF[mt][1], aF[mt][2], aF[mt][3], b0, b1);
            }
        }

        b0a = b1a; b0b = b1b;
        b1a = b2a; b1b = b2b;
    }

    // ---- epilogue ----
    const int mwarp = (wid & 3) * 32;
    const int nwarp = (wid >> 2) * 64;
#pragma unroll
    for (int nt = 0; nt < 8; nt++) {
        const int col = n0 + nwarp + nt * 8 + 2 * t;
        const float2 bb = *(const float2*)(bias + col);
#pragma unroll
        for (int mt = 0; mt < 2; mt++) {
            const int row0 = m0 + mwarp + mt * 16 + g;
            *(float2*)(out + (size_t)row0 * N + col) =
                make_float2(acc[mt][nt][0] + bb.x, acc[mt][nt][1] + bb.y);
            *(float2*)(out + (size_t)(row0 + 8) * N + col) =
                make_float2(acc[mt][nt][2] + bb.x, acc[mt][nt][3] + bb.y);
        }
    }
}

extern "C" void kernel_launch(void* const* d_in, const int* in_sizes, int n_in,
                              void* d_out, int out_size)
{
    const float* x      = (const float*)d_in[0];
    const int*   qw     = (const int*)d_in[1];
    const int*   zeros  = (const int*)d_in[2];
    const float* scales = (const float*)d_in[3];
    const float* bias   = (const float*)d_in[4];
    float* out = (float*)d_out;

    const int N = in_sizes[4];                                   // 11008
    const int K = (int)(((long long)in_sizes[1] * 8) / N);       // 4096
    const int M = in_sizes[0] / K;                               // 4096

    const int slabs = (M / 16) * (K / 16);
    xprep_kernel<<<slabs / 4, 128>>>(x, M, K);

    cudaFuncSetAttribute(wq4_mma_kernel,
                         cudaFuncAttributeMaxDynamicSharedMemorySize, SMEM_BYTES);
    dim3 grid(N / BN, M / BM);
    wq4_mma_kernel<<<grid, THREADS, SMEM_BYTES>>>(qw, zeros, scales, bias, out, M, K, N);
}